// round 12
// baseline (speedup 1.0000x reference)
#include <cuda_runtime.h>
#include <cuda_bf16.h>
#include <math.h>
#include <cstdint>

// ----------------------------------------------------------------------------
// FNO-GNO forward, sm_103. Round 12: round-11 with the pair-interleave smem
// stride fixed 132 -> 136 uint2 (8·tig bank phase => conflict-free LDS.64).
// ----------------------------------------------------------------------------

#define S 54
#define S2 2916
#define S3 157464
#define CH 86
#define CS 13541904        // 86 * S3
#define NOUT 110592        // 48^3
#define NIN 8192
#define KNB 24
#define RTOT 196608        // NIN*KNB
#define MO 6
#define Q72 72
#define NMODE 864
#define WLAYER 6390144     // 4*216*86*86 (float2 per layer)
#define EPSGN 1e-5

// ---------------- device scratch ---------------------------------------------
__device__ float  g_h   [CS];
__device__ float  g_skip[CS];
__device__ float  g_hf  [CS];
__device__ float  g_t1  [CS];
__device__ float2 g_A1[CH*S2*MO];
__device__ float2 g_A2[CH*S*Q72];
__device__ float2 g_A3[CH*NMODE];
__device__ float2 g_M3[CH*NMODE];
__device__ float2 g_B2[CH*S*Q72];
__device__ float2 g_B1[CH*S2*MO];
__device__ float2 g_wp[4*WLAYER];
__device__ float  g_xoe[(size_t)NOUT*48];
__device__ float  g_xie[(size_t)NIN*48];
__device__ float  g_fy [(size_t)NOUT*CH];
__device__ float  g_y1 [(size_t)NOUT*512];
__device__ float  g_q1 [(size_t)NIN*512];
__device__ float  g_k1 [(size_t)RTOT*512];
__device__ float  g_k2 [(size_t)RTOT*256];
__device__ float  g_k3 [(size_t)RTOT*CH];
__device__ float  g_gv [(size_t)NIN*CH];
__device__ float  g_p1 [(size_t)NIN*256];
__device__ float  g_twy[48*512];
__device__ float  g_twq[48*512];
__device__ float  g_tw2[512*256];
__device__ float  g_tw3[256*88];
__device__ float  g_twp[86*256];
__device__ int    g_cnt [NIN];
__device__ int    g_base[NIN];
__device__ int    g_ci  [RTOT];
__device__ int    g_cnb [RTOT];
__device__ int    g_mtot[4];
__device__ double g_stats[2];
__device__ float  d_c12[648], d_s12[648];
__device__ int    g_mask_fmt;

__device__ __forceinline__ float gelu_f(float x){
    return 0.5f*x*(1.0f+erff(x*0.7071067811865476f));
}

// ---------------- bf16 mma helpers --------------------------------------------
__device__ __forceinline__ uint32_t pack_hi(float x0, float x1,
                                            float& r0, float& r1){
    __nv_bfloat16 h0 = __float2bfloat16(x0);
    __nv_bfloat16 h1 = __float2bfloat16(x1);
    r0 = x0 - __bfloat162float(h0);
    r1 = x1 - __bfloat162float(h1);
    __nv_bfloat162 t = __halves2bfloat162(h0, h1);
    return *(uint32_t*)&t;
}
__device__ __forceinline__ uint32_t pack_bf(float x0, float x1){
    __nv_bfloat162 t = __floats2bfloat162_rn(x0, x1);
    return *(uint32_t*)&t;
}
__device__ __forceinline__ void mma_bf16(float* c, const uint32_t* a, const uint32_t* b){
    asm volatile(
        "mma.sync.aligned.m16n8k16.row.col.f32.bf16.bf16.f32 "
        "{%0,%1,%2,%3}, {%4,%5,%6,%7}, {%8,%9}, {%0,%1,%2,%3};"
        : "+f"(c[0]),"+f"(c[1]),"+f"(c[2]),"+f"(c[3])
        : "r"(a[0]),"r"(a[1]),"r"(a[2]),"r"(a[3]), "r"(b[0]),"r"(b[1]));
}

// ---------------- mask dtype detection ---------------------------------------
__global__ void detect_mask_k(const unsigned char* __restrict__ m){
    __shared__ int s_f1, s_f3, s_nzna, s_oddw;
    if(threadIdx.x==0){ s_f1=0; s_f3=0; s_nzna=0; s_oddw=0; }
    __syncthreads();
    for(int i=threadIdx.x; i<4096; i+=blockDim.x){
        unsigned char b = m[i];
        int off = i & 3;
        if(b){
            if(off==1 && b==0x3F) atomicOr(&s_f1, 1);
            if(off==3 && b==0x3F) atomicOr(&s_f3, 1);
            if(off!=0)            atomicOr(&s_nzna, 1);
        }
    }
    const unsigned int* w = (const unsigned int*)m;
    for(int i=threadIdx.x; i<1024; i+=blockDim.x){
        if((i & 1) && w[i]) atomicOr(&s_oddw, 1);
    }
    __syncthreads();
    if(threadIdx.x==0){
        int fmt;
        if(s_f1)        fmt = 3;
        else if(s_f3)   fmt = 2;
        else if(s_nzna) fmt = 0;
        else if(s_oddw) fmt = 1;
        else            fmt = 4;
        g_mask_fmt = fmt;
    }
}
__device__ __forceinline__ int mask_at(const void* p, long r, int fmt){
    switch(fmt){
        case 0: return ((const unsigned char*)p)[r] != 0;
        case 1: return ((const int*)p)[r] != 0;
        case 2: return ((const float*)p)[r] != 0.f;
        case 3: return ((const unsigned short*)p)[r] != 0;
        default:return ((const long long*)p)[r] != 0;
    }
}

// ---------------- compaction ---------------------------------------------------
__global__ void count_k(const void* __restrict__ nb_mask){
    int i = blockIdx.x*256 + threadIdx.x;
    if(i >= NIN) return;
    int fmt = g_mask_fmt;
    int c = 0;
    for(int j=0;j<KNB;j++) c += mask_at(nb_mask, (long)i*KNB + j, fmt);
    g_cnt[i] = c;
}

__global__ void scan_k(){
    __shared__ int part[256];
    int t = threadIdx.x;
    int local[32];
    int s = 0;
    #pragma unroll
    for(int u=0;u<32;u++){
        local[u] = s;
        s += g_cnt[t*32 + u];
    }
    part[t] = s;
    __syncthreads();
    if(t == 0){
        int run = 0;
        for(int k=0;k<256;k++){ int v = part[k]; part[k] = run; run += v; }
        g_mtot[0] = run;
    }
    __syncthreads();
    int off = part[t];
    #pragma unroll
    for(int u=0;u<32;u++) g_base[t*32 + u] = off + local[u];
}

__global__ void fill_k(const int* __restrict__ nb_idx, const void* __restrict__ nb_mask){
    int i = blockIdx.x*256 + threadIdx.x;
    if(i >= NIN) return;
    int fmt = g_mask_fmt;
    int base = g_base[i], p = 0;
    for(int j=0;j<KNB;j++){
        if(mask_at(nb_mask, (long)i*KNB + j, fmt)){
            g_ci [base+p] = i;
            g_cnb[base+p] = nb_idx[i*KNB + j];
            p++;
        }
    }
}

// ---------------- prep -------------------------------------------------------
__global__ void basis_k(){
    int t = blockIdx.x*blockDim.x + threadIdx.x;
    if(t >= 648) return;
    int p = t/54, z = t%54;
    int ef = (p<6) ? p : (p+42);
    int m = (ef*z) % 54;
    double th = 6.283185307179586476925286766559 * (double)m / 54.0;
    d_c12[t] = (float)cos(th);
    d_s12[t] = (float)sin(th);
}
__global__ void zero_stats_k(){ g_stats[0]=0.0; g_stats[1]=0.0; }

__global__ void repack_k(const float* __restrict__ wr, const float* __restrict__ wi){
    long idx = (long)blockIdx.x*256 + threadIdx.x;
    if(idx >= 25560576L) return;
    long x = idx;
    int o = (int)(x%86); x/=86;
    int i = (int)(x%86); x/=86;
    int mloc = (int)(x%216); x/=216;
    long lb = x;
    long src = ((lb*86 + i)*86 + o)*216 + mloc;
    g_wp[idx] = make_float2(wr[src], wi[src]);
}

__global__ void transpose_k(const float* __restrict__ src, float* __restrict__ dst,
                            int O, int Kt, int Ktot, int k0, int ldd){
    int t = blockIdx.x*256 + threadIdx.x;
    if(t >= O*Kt) return;
    int k = t / O, o = t % O;
    dst[(size_t)k*ldd + o] = src[(size_t)o*Ktot + k0 + k];
}

// ---------------- lift --------------------------------------------------------
__global__ void lift_k(const float* __restrict__ df, const float* __restrict__ xout,
                       const float* __restrict__ w, const float* __restrict__ b){
    int n = blockIdx.x*256 + threadIdx.x;
    int c = blockIdx.y;
    if(n >= S3) return;
    int i = n/S2, j = (n/S)%S, k = n%S;
    float v = 0.f;
    if(i < 48 && j < 48 && k < 48){
        int n48 = (i*48 + j)*48 + k;
        float f0 = df[n48], f1 = df[NOUT + n48];
        float f2 = xout[n48*3+0], f3 = xout[n48*3+1], f4 = xout[n48*3+2];
        const float* wr = &w[c*5];
        v = b[c] + wr[0]*f0 + wr[1]*f1 + wr[2]*f2 + wr[3]*f3 + wr[4]*f4;
    }
    g_h[(size_t)c*S3 + n] = v;
}

// ---------------- bf16x3 tensor GEMM (pair-interleaved smem, LDS.64 frags) ----
// C[M,N](ldc=N) = act( W[M,K](lda) @ X[K,N](ldx) + bias )
template<int BIASCOL, int ACT, int STATS>
__global__ __launch_bounds__(256, 2) void bgemm_k(
    const float* __restrict__ W, int lda,
    const float* __restrict__ X, int ldx,
    const float* __restrict__ Bv, float* __restrict__ C,
    int M, int K, int N, const int* __restrict__ Mdev)
{
    if(Mdev) M = *Mdev;
    const int bm = blockIdx.y*128, bn = blockIdx.x*128;
    if(bm >= M) return;
    // pair-interleaved: [buf][pair 0..3][idx] uint2 {word kw=pair, word kw=pair+4}
    // stride 136: 136*tig mod 32 = 8*tig -> conflict-free 8B-bank access
    __shared__ uint2 aH2[2][4][136], aL2[2][4][136];
    __shared__ uint2 bH2[2][4][136], bL2[2][4][136];
    const int tid = threadIdx.x;
    const int wid = tid>>5, lane = tid&31;
    const int gid = lane>>2, tig = lane&3;
    const int wm = (wid>>1)*32;
    const int wn = (wid&1)*64;

    float acc[2][8][4];
    #pragma unroll
    for(int a=0;a<2;a++)
        #pragma unroll
        for(int b=0;b<8;b++)
            #pragma unroll
            for(int c=0;c<4;c++) acc[a][b][c]=0.f;

    const int am   = tid & 127;
    const int akw0 = tid >> 7;
    const int wb  = wid;
    const int pB  = wb & 3;
    const int chB = wb >> 2;
    const int cnB = chB*64 + lane*2;

    float  a0[4], a1[4];
    float2 xv0, xv1, xv2, xv3;

    auto loadT = [&](int kt){
        int k0 = kt*16;
        int gm = bm + am;
        #pragma unroll
        for(int u=0;u<4;u++){
            int gk = k0 + (akw0 + 2*u)*2;
            if(gm < M && gk+1 < K){
                float2 v = *(const float2*)&W[(size_t)gm*lda + gk];
                a0[u] = v.x; a1[u] = v.y;
            } else { a0[u]=0.f; a1[u]=0.f; }
        }
        int gn = bn + cnB;
        int gk0 = k0 + 2*pB;
        xv0 = make_float2(0.f,0.f); xv1 = make_float2(0.f,0.f);
        xv2 = make_float2(0.f,0.f); xv3 = make_float2(0.f,0.f);
        if(gn + 1 < N){
            if(gk0   < K) xv0 = *(const float2*)&X[(size_t)(gk0  )*ldx + gn];
            if(gk0+1 < K) xv1 = *(const float2*)&X[(size_t)(gk0+1)*ldx + gn];
            if(gk0+8 < K) xv2 = *(const float2*)&X[(size_t)(gk0+8)*ldx + gn];
            if(gk0+9 < K) xv3 = *(const float2*)&X[(size_t)(gk0+9)*ldx + gn];
        } else if(gn < N){
            if(gk0   < K) xv0.x = X[(size_t)(gk0  )*ldx + gn];
            if(gk0+1 < K) xv1.x = X[(size_t)(gk0+1)*ldx + gn];
            if(gk0+8 < K) xv2.x = X[(size_t)(gk0+8)*ldx + gn];
            if(gk0+9 < K) xv3.x = X[(size_t)(gk0+9)*ldx + gn];
        }
    };
    auto storeT = [&](int b){
        #pragma unroll
        for(int v=0;v<2;v++){
            int p = akw0 + 2*v;
            float l0,l1,m0,m1;
            uint32_t hlo = pack_hi(a0[v],   a1[v],   l0, l1);
            uint32_t hhi = pack_hi(a0[v+2], a1[v+2], m0, m1);
            aH2[b][p][am] = make_uint2(hlo, hhi);
            aL2[b][p][am] = make_uint2(pack_bf(l0,l1), pack_bf(m0,m1));
        }
        float l0,l1;
        uint32_t hx0 = pack_hi(xv0.x, xv1.x, l0, l1); uint32_t lx0 = pack_bf(l0,l1);
        uint32_t hy0 = pack_hi(xv2.x, xv3.x, l0, l1); uint32_t ly0 = pack_bf(l0,l1);
        uint32_t hx1 = pack_hi(xv0.y, xv1.y, l0, l1); uint32_t lx1 = pack_bf(l0,l1);
        uint32_t hy1 = pack_hi(xv2.y, xv3.y, l0, l1); uint32_t ly1 = pack_bf(l0,l1);
        *(uint4*)&bH2[b][pB][cnB] = make_uint4(hx0,hy0,hx1,hy1);
        *(uint4*)&bL2[b][pB][cnB] = make_uint4(lx0,ly0,lx1,ly1);
    };
    auto comp = [&](int b){
        uint32_t ah[2][4], al[2][4];
        #pragma unroll
        for(int mt=0; mt<2; mt++){
            int r0 = wm + mt*16 + gid;
            uint2 q0 = aH2[b][tig][r0];
            uint2 q1 = aH2[b][tig][r0+8];
            ah[mt][0]=q0.x; ah[mt][2]=q0.y; ah[mt][1]=q1.x; ah[mt][3]=q1.y;
            uint2 p0 = aL2[b][tig][r0];
            uint2 p1 = aL2[b][tig][r0+8];
            al[mt][0]=p0.x; al[mt][2]=p0.y; al[mt][1]=p1.x; al[mt][3]=p1.y;
        }
        #pragma unroll
        for(int nt=0; nt<8; nt++){
            int cn = wn + nt*8 + gid;
            uint2 qb = bH2[b][tig][cn];
            uint2 ql = bL2[b][tig][cn];
            uint32_t bh2[2] = {qb.x, qb.y};
            uint32_t bl2[2] = {ql.x, ql.y};
            #pragma unroll
            for(int mt=0; mt<2; mt++){
                mma_bf16(acc[mt][nt], ah[mt], bh2);
                mma_bf16(acc[mt][nt], ah[mt], bl2);
                mma_bf16(acc[mt][nt], al[mt], bh2);
            }
        }
    };

    int ntiles = (K+15)>>4;
    loadT(0); storeT(0);
    __syncthreads();
    int buf = 0;
    for(int t=1; t<ntiles; t++){
        loadT(t);
        comp(buf);
        storeT(buf^1);
        __syncthreads();
        buf ^= 1;
    }
    comp(buf);

    float ssum = 0.f, ssq = 0.f;
    #pragma unroll
    for(int mt=0; mt<2; mt++){
        int r0 = bm + wm + mt*16 + gid;
        int r1 = r0 + 8;
        float rb0 = 0.f, rb1 = 0.f;
        if(!BIASCOL && Bv){
            if(r0 < M) rb0 = Bv[r0];
            if(r1 < M) rb1 = Bv[r1];
        }
        #pragma unroll
        for(int nt=0; nt<8; nt++){
            int gn = bn + wn + nt*8 + tig*2;
            float cb0 = 0.f, cb1 = 0.f;
            if(BIASCOL && Bv){
                if(gn   < N) cb0 = Bv[gn];
                if(gn+1 < N) cb1 = Bv[gn+1];
            }
            float v0 = acc[mt][nt][0] + (BIASCOL ? cb0 : rb0);
            float v1 = acc[mt][nt][1] + (BIASCOL ? cb1 : rb0);
            float v2 = acc[mt][nt][2] + (BIASCOL ? cb0 : rb1);
            float v3 = acc[mt][nt][3] + (BIASCOL ? cb1 : rb1);
            if(ACT){ v0=gelu_f(v0); v1=gelu_f(v1); v2=gelu_f(v2); v3=gelu_f(v3); }
            if(r0 < M){
                if(gn   < N){ C[(size_t)r0*N + gn]   = v0; if(STATS){ ssum+=v0; ssq=fmaf(v0,v0,ssq);} }
                if(gn+1 < N){ C[(size_t)r0*N + gn+1] = v1; if(STATS){ ssum+=v1; ssq=fmaf(v1,v1,ssq);} }
            }
            if(r1 < M){
                if(gn   < N){ C[(size_t)r1*N + gn]   = v2; if(STATS){ ssum+=v2; ssq=fmaf(v2,v2,ssq);} }
                if(gn+1 < N){ C[(size_t)r1*N + gn+1] = v3; if(STATS){ ssum+=v3; ssq=fmaf(v3,v3,ssq);} }
            }
        }
    }
    if(STATS){
        #pragma unroll
        for(int o=16;o>0;o>>=1){
            ssum += __shfl_down_sync(0xffffffffu, ssum, o);
            ssq  += __shfl_down_sync(0xffffffffu, ssq,  o);
        }
        __shared__ double ds[8], ds2[8];
        if(lane==0){ ds[wid]=(double)ssum; ds2[wid]=(double)ssq; }
        __syncthreads();
        if(tid==0){
            double a=0,b=0;
            #pragma unroll
            for(int k=0;k<8;k++){ a+=ds[k]; b+=ds2[k]; }
            atomicAdd(&g_stats[0], a);
            atomicAdd(&g_stats[1], b);
        }
    }
}

// ---------------- partial DFT chain (col-major h) ------------------------------
__global__ void dft_z_k(const float* __restrict__ h){
    __shared__ float sh[32*54];
    __shared__ float bc[324], bs[324];
    int t = threadIdx.x;                // 192
    long rowbase = (long)blockIdx.x*32;
    for(int i=t;i<324;i+=192){ bc[i]=d_c12[i]; bs[i]=d_s12[i]; }
    long gbase = rowbase*54;
    const long TOT = (long)CH*S2*54;
    for(int i=t;i<32*54;i+=192){
        long g = gbase + i;
        sh[i] = (g < TOT) ? h[g] : 0.f;
    }
    __syncthreads();
    int r = t/6, kz = t%6;
    long row = rowbase + r;
    if(row < (long)CH*S2){
        float re=0.f, im=0.f;
        const float* x = &sh[r*54];
        #pragma unroll
        for(int z=0;z<54;z++){
            float v = x[z];
            re = fmaf(v, bc[kz*54+z], re);
            im = fmaf(-v, bs[kz*54+z], im);
        }
        g_A1[row*6+kz] = make_float2(re, im);
    }
}

__global__ void dft_y_k(){
    __shared__ float2 sh[324];
    int t = threadIdx.x;                // 128
    int cx = blockIdx.x;
    const float2* src = g_A1 + (size_t)cx*324;
    for(int i=t;i<324;i+=128) sh[i] = src[i];
    __syncthreads();
    if(t < 72){
        int ky = t/6, kz = t%6;
        float re=0.f, im=0.f;
        for(int y=0;y<54;y++){
            float2 v = sh[y*6+kz];
            float c = d_c12[ky*54+y], s = d_s12[ky*54+y];
            re += v.x*c + v.y*s;
            im += v.y*c - v.x*s;
        }
        g_A2[(size_t)cx*72 + t] = make_float2(re, im);
    }
}

__global__ void dft_x_k(){
    __shared__ float2 sh[S*Q72];
    int t = threadIdx.x;                // 256
    int c = blockIdx.x;
    const float2* src = g_A2 + (size_t)c*(S*Q72);
    for(int i=t;i<S*Q72;i+=256) sh[i] = src[i];
    __syncthreads();
    for(int u=t; u<NMODE; u+=256){
        int kx = u/72, q = u%72;
        float re=0.f, im=0.f;
        for(int x=0;x<54;x++){
            float2 v = sh[x*72+q];
            float cc = d_c12[kx*54+x], s = d_s12[kx*54+x];
            re += v.x*cc + v.y*s;
            im += v.y*cc - v.x*s;
        }
        g_A3[(size_t)c*NMODE + u] = make_float2(re, im);
    }
}

__global__ void mix_k(const float2* __restrict__ wp){
    __shared__ float2 a[86];
    int m = blockIdx.x;                 // 864
    int t = threadIdx.x;                // 96
    int kx = m/72, ky = (m%72)/6, kz = m%6;
    if(t < 86) a[t] = g_A3[(size_t)t*NMODE + m];
    __syncthreads();
    if(t < 86){
        int cblk = (kx>=6)*2 + (ky>=6);
        int mloc = (kx%6)*36 + (ky%6)*6 + kz;
        const float2* w = wp + ((size_t)cblk*216 + mloc)*7396 + t;
        float re=0.f, im=0.f;
        for(int i=0;i<86;i++){
            float2 av = a[i];
            float2 wv = w[(size_t)i*86];
            re += av.x*wv.x - av.y*wv.y;
            im += av.x*wv.y + av.y*wv.x;
        }
        g_M3[(size_t)t*NMODE + m] = make_float2(re, im);
    }
}

__global__ void inv_x_k(){
    __shared__ float2 sh[NMODE];
    int t = threadIdx.x;                // 256
    int c = blockIdx.x;
    for(int i=t;i<NMODE;i+=256) sh[i] = g_M3[(size_t)c*NMODE + i];
    __syncthreads();
    for(int u=t; u<S*Q72; u+=256){
        int x = u/72, q = u%72;
        float re=0.f, im=0.f;
        #pragma unroll
        for(int p=0;p<12;p++){
            float2 v = sh[p*72+q];
            float cc = d_c12[p*54+x], s = d_s12[p*54+x];
            re += v.x*cc - v.y*s;
            im += v.x*s  + v.y*cc;
        }
        g_B2[(size_t)c*(S*Q72) + u] = make_float2(re, im);
    }
}

__global__ void inv_y_k(){
    __shared__ float2 sh[72];
    int t = threadIdx.x;                // 128
    int cx = blockIdx.x;
    if(t < 72) sh[t] = g_B2[(size_t)cx*72 + t];
    __syncthreads();
    for(int u=t; u<324; u+=128){
        int y = u/6, kz = u%6;
        float re=0.f, im=0.f;
        #pragma unroll
        for(int ky=0;ky<12;ky++){
            float2 v = sh[ky*6+kz];
            float cc = d_c12[ky*54+y], s = d_s12[ky*54+y];
            re += v.x*cc - v.y*s;
            im += v.x*s  + v.y*cc;
        }
        g_B1[(size_t)cx*324 + u] = make_float2(re, im);
    }
}

__global__ void inv_z_k(){
    __shared__ float2 sh[324];
    int t = threadIdx.x;                // 256
    int cx = blockIdx.x;
    for(int i=t;i<324;i+=256) sh[i] = g_B1[(size_t)cx*324 + i];
    __syncthreads();
    const float inv = 1.0f/157464.0f;
    float ssum=0.f, ssq=0.f;
    for(int u=t; u<S2; u+=256){
        int y = u/54, z = u%54;
        const float2* b = &sh[y*6];
        float v = b[0].x;
        #pragma unroll
        for(int kz=1;kz<6;kz++){
            float cc = d_c12[kz*54+z], s = d_s12[kz*54+z];
            v += 2.f*(b[kz].x*cc - b[kz].y*s);
        }
        v *= inv;
        g_hf[(size_t)cx*S2 + u] = v;
        ssum += v; ssq = fmaf(v,v,ssq);
    }
    #pragma unroll
    for(int o=16;o>0;o>>=1){
        ssum += __shfl_down_sync(0xffffffffu, ssum, o);
        ssq  += __shfl_down_sync(0xffffffffu, ssq,  o);
    }
    __shared__ double ds[8], ds2[8];
    int w = t>>5;
    if((t&31)==0){ ds[w]=(double)ssum; ds2[w]=(double)ssq; }
    __syncthreads();
    if(t==0){
        double a=0,b=0;
        #pragma unroll
        for(int k=0;k<8;k++){ a+=ds[k]; b+=ds2[k]; }
        atomicAdd(&g_stats[0], a);
        atomicAdd(&g_stats[1], b);
    }
}

// ---------------- combine ------------------------------------------------------
__global__ void combine_k(const float4* __restrict__ buf, const float4* __restrict__ add,
                          const float* __restrict__ gw, const float* __restrict__ gb,
                          float4* __restrict__ h, int actflag){
    long i = (long)blockIdx.x*blockDim.x + threadIdx.x;
    if(i >= (CS>>2)) return;
    double mu  = g_stats[0]/(double)CS;
    double var = g_stats[1]/(double)CS - mu*mu;
    float rs = (float)rsqrt(var + EPSGN);
    float fmu = (float)mu;
    int c = (int)((i<<2) / S3);
    float sw = rs*gw[c], sb = gb[c];
    float4 u = buf[i], a = add[i];
    float4 o;
    o.x = (u.x-fmu)*sw + sb + a.x;
    o.y = (u.y-fmu)*sw + sb + a.y;
    o.z = (u.z-fmu)*sw + sb + a.z;
    o.w = (u.w-fmu)*sw + sb + a.w;
    if(actflag){ o.x=gelu_f(o.x); o.y=gelu_f(o.y); o.z=gelu_f(o.z); o.w=gelu_f(o.w); }
    h[i] = o;
}

// ---------------- GNO head (row-major, compacted) ------------------------------
__global__ void embed_k(const float* __restrict__ pts, float* __restrict__ out, int n){
    int i = blockIdx.x*blockDim.x + threadIdx.x;
    if(i >= n) return;
    #pragma unroll
    for(int d=0; d<3; d++){
        float x = pts[i*3+d];
        #pragma unroll
        for(int f=0; f<8; f++){
            float fr = powf(1e-4f, (float)f/8.0f);
            float a = x*fr;
            out[(size_t)i*48 + d*16 + f]     = cosf(a);
            out[(size_t)i*48 + d*16 + 8 + f] = sinf(a);
        }
    }
}

__global__ void crop_k(){
    int n = blockIdx.x*256 + threadIdx.x;
    int c = blockIdx.y;
    if(n >= NOUT) return;
    int i = n/2304, j = (n/48)%48, k = n%48;
    g_fy[(size_t)n*CH + c] = g_h[((size_t)(c*S + i)*S + j)*S + k];
}

__global__ void k1_fuse_k(){
    long gt = (long)blockIdx.x*256 + threadIdx.x;
    int s  = (int)(gt >> 7);
    if(s >= g_mtot[0]) return;
    int c4 = ((int)gt & 127) << 2;
    int idx = g_cnb[s];
    int i = g_ci[s];
    float4 y = *(const float4*)&g_y1[(size_t)idx*512 + c4];
    float4 q = *(const float4*)&g_q1[(size_t)i*512 + c4];
    float4 o;
    o.x = gelu_f(y.x+q.x); o.y = gelu_f(y.y+q.y);
    o.z = gelu_f(y.z+q.z); o.w = gelu_f(y.w+q.w);
    *(float4*)&g_k1[(size_t)s*512 + c4] = o;
}

__global__ void gno_reduce_k(){
    int i = blockIdx.x;                 // NIN
    int c = threadIdx.x;                // 96 (86 active)
    __shared__ int sidx[KNB];
    __shared__ int sbase, scnt;
    if(c == 0){ sbase = g_base[i]; scnt = g_cnt[i]; }
    __syncthreads();
    if(c < scnt) sidx[c] = g_cnb[sbase + c];
    __syncthreads();
    if(c >= CH) return;
    float acc = 0.f;
    int cnt = scnt;
    for(int j=0; j<cnt; j++){
        acc += g_k3[((size_t)(sbase+j))*CH + c] * g_fy[(size_t)sidx[j]*CH + c];
    }
    float den = (float)(cnt > 1 ? cnt : 1);
    g_gv[(size_t)i*CH + c] = acc/den;
}

__global__ void p2_k(const float* __restrict__ w, const float* __restrict__ b,
                     float* __restrict__ out){
    int warp = threadIdx.x>>5, lane = threadIdx.x&31;
    int row = blockIdx.x*8 + warp;
    if(row >= NIN) return;
    const float* pr = g_p1 + (size_t)row*256;
    float acc = 0.f;
    #pragma unroll
    for(int f=lane; f<256; f+=32) acc = fmaf(w[f], pr[f], acc);
    #pragma unroll
    for(int o=16;o>0;o>>=1) acc += __shfl_down_sync(0xffffffffu, acc, o);
    if(lane==0) out[row] = acc + b[0];
}

// ---------------- host orchestration -----------------------------------------
static void bgemm(const float* W, int lda, const float* X, int ldx,
                  const float* B, float* C,
                  int M, int K, int N, int act, int biascol, int stats,
                  const int* Mdev = 0){
    dim3 grid((N+127)/128, (M+127)/128);
    if(biascol){
        if(act) bgemm_k<1,1,0><<<grid,256>>>(W,lda,X,ldx,B,C,M,K,N,Mdev);
        else    bgemm_k<1,0,0><<<grid,256>>>(W,lda,X,ldx,B,C,M,K,N,Mdev);
    } else if(stats){
        bgemm_k<0,0,1><<<grid,256>>>(W,lda,X,ldx,B,C,M,K,N,Mdev);
    } else {
        if(act) bgemm_k<0,1,0><<<grid,256>>>(W,lda,X,ldx,B,C,M,K,N,Mdev);
        else    bgemm_k<0,0,0><<<grid,256>>>(W,lda,X,ldx,B,C,M,K,N,Mdev);
    }
}

extern "C" void kernel_launch(void* const* d_in, const int* in_sizes, int n_in,
                              void* d_out, int out_size){
    const float* x_in   = (const float*)d_in[0];
    const float* x_out  = (const float*)d_in[1];
    const float* df     = (const float*)d_in[2];
    const int*   nb_idx = (const int*)  d_in[3];
    const void*  nb_mask= (const void*) d_in[4];
    const float* w_lift = (const float*)d_in[5];
    const float* b_lift = (const float*)d_in[6];
    const float* spec_wr= (const float*)d_in[7];
    const float* spec_wi= (const float*)d_in[8];
    const float* w_skip = (const float*)d_in[9];
    const float* b_skip = (const float*)d_in[10];
    const float* mlp1_w = (const float*)d_in[11];
    const float* mlp1_b = (const float*)d_in[12];
    const float* mlp2_w = (const float*)d_in[13];
    const float* mlp2_b = (const float*)d_in[14];
    const float* wms    = (const float*)d_in[15];
    const float* bms    = (const float*)d_in[16];
    const float* g1w    = (const float*)d_in[17];
    const float* g1b    = (const float*)d_in[18];
    const float* g2w    = (const float*)d_in[19];
    const float* g2b    = (const float*)d_in[20];
    const float* k1w    = (const float*)d_in[21];
    const float* k1b    = (const float*)d_in[22];
    const float* k2w    = (const float*)d_in[23];
    const float* k2b    = (const float*)d_in[24];
    const float* k3w    = (const float*)d_in[25];
    const float* k3b    = (const float*)d_in[26];
    const float* p1w    = (const float*)d_in[27];
    const float* p1b    = (const float*)d_in[28];
    const float* p2w    = (const float*)d_in[29];
    const float* p2b    = (const float*)d_in[30];
    float* out = (float*)d_out;

    float *ph, *pskip, *phf, *pt1, *pxoe, *pxie, *py1, *pq1, *pk1, *pk2, *pk3, *pgv, *pp1;
    float *ptwy, *ptwq, *ptw2, *ptw3, *ptwp;
    float2 *pwp;
    int *pmtot;
    cudaGetSymbolAddress((void**)&ph,    g_h);
    cudaGetSymbolAddress((void**)&pskip, g_skip);
    cudaGetSymbolAddress((void**)&phf,   g_hf);
    cudaGetSymbolAddress((void**)&pt1,   g_t1);
    cudaGetSymbolAddress((void**)&pxoe,  g_xoe);
    cudaGetSymbolAddress((void**)&pxie,  g_xie);
    cudaGetSymbolAddress((void**)&py1,   g_y1);
    cudaGetSymbolAddress((void**)&pq1,   g_q1);
    cudaGetSymbolAddress((void**)&pk1,   g_k1);
    cudaGetSymbolAddress((void**)&pk2,   g_k2);
    cudaGetSymbolAddress((void**)&pk3,   g_k3);
    cudaGetSymbolAddress((void**)&pgv,   g_gv);
    cudaGetSymbolAddress((void**)&pp1,   g_p1);
    cudaGetSymbolAddress((void**)&ptwy,  g_twy);
    cudaGetSymbolAddress((void**)&ptwq,  g_twq);
    cudaGetSymbolAddress((void**)&ptw2,  g_tw2);
    cudaGetSymbolAddress((void**)&ptw3,  g_tw3);
    cudaGetSymbolAddress((void**)&ptwp,  g_twp);
    cudaGetSymbolAddress((void**)&pwp,   g_wp);
    cudaGetSymbolAddress((void**)&pmtot, g_mtot);

    // prep
    basis_k<<<2,384>>>();
    detect_mask_k<<<1,256>>>((const unsigned char*)nb_mask);
    count_k<<<NIN/256,256>>>(nb_mask);
    scan_k<<<1,256>>>();
    fill_k<<<NIN/256,256>>>(nb_idx, nb_mask);
    {
        dim3 g((S3+255)/256, CH);
        lift_k<<<g,256>>>(df, x_out, w_lift, b_lift);
    }
    bgemm(w_skip, CH, ph, S3, b_skip, pskip, CH, CH, S3, 0, 0, 0);
    repack_k<<<(int)((25560576L+255)/256),256>>>(spec_wr, spec_wi);
    transpose_k<<<(512*48 +255)/256,256>>>(k1w, ptwy, 512,  48,  96, 0,  512);
    transpose_k<<<(512*48 +255)/256,256>>>(k1w, ptwq, 512,  48,  96, 48, 512);
    transpose_k<<<(256*512+255)/256,256>>>(k2w, ptw2, 256, 512, 512, 0,  256);
    transpose_k<<<(86*256 +255)/256,256>>>(k3w, ptw3,  86, 256, 256, 0,   88);
    transpose_k<<<(256*86 +255)/256,256>>>(p1w, ptwp, 256,  86,  86, 0,  256);

    // FNO layers
    for(int l=0;l<4;l++){
        int act = (l<3) ? 1 : 0;
        if(l > 0)
            bgemm(w_skip + (size_t)l*CH*CH, CH, ph, S3, b_skip + l*CH, pskip, CH, CH, S3, 0, 0, 0);
        dft_z_k<<<(CH*S2+31)/32, 192>>>(ph);
        dft_y_k<<<CH*S, 128>>>();
        dft_x_k<<<CH, 256>>>();
        mix_k<<<NMODE, 96>>>(pwp + (size_t)l*WLAYER);
        inv_x_k<<<CH, 256>>>();
        inv_y_k<<<CH*S, 128>>>();
        zero_stats_k<<<1,1>>>();
        inv_z_k<<<CH*S, 256>>>();
        combine_k<<<((CS>>2)+255)/256,256>>>((const float4*)phf,(const float4*)pskip,
                                             g1w + l*CH, g1b + l*CH, (float4*)ph, act);
        bgemm(wms    + (size_t)l*CH*CH, CH, ph,  S3, bms    + l*CH, pskip, CH, CH, S3, 0, 0, 0);
        bgemm(mlp1_w + (size_t)l*CH*CH, CH, ph,  S3, mlp1_b + l*CH, pt1,   CH, CH, S3, 1, 0, 0);
        zero_stats_k<<<1,1>>>();
        bgemm(mlp2_w + (size_t)l*CH*CH, CH, pt1, S3, mlp2_b + l*CH, phf,   CH, CH, S3, 0, 0, 1);
        combine_k<<<((CS>>2)+255)/256,256>>>((const float4*)phf,(const float4*)pskip,
                                             g2w + l*CH, g2b + l*CH, (float4*)ph, act);
    }

    // crop f_y
    {
        dim3 g((NOUT+255)/256, CH);
        crop_k<<<g,256>>>();
    }

    // row-major embeddings
    embed_k<<<(NOUT+127)/128,128>>>(x_out, pxoe, NOUT);
    embed_k<<<(NIN +127)/128,128>>>(x_in,  pxie, NIN);

    // GNO kernel MLP on compacted rows
    bgemm(pxoe, 48, ptwy, 512, 0,   py1, NOUT, 48, 512, 0, 1, 0);
    bgemm(pxie, 48, ptwq, 512, k1b, pq1, NIN,  48, 512, 0, 1, 0);
    k1_fuse_k<<<(int)(((long)RTOT*128)/256),256>>>();
    bgemm(pk1, 512, ptw2, 256, k2b, pk2, RTOT, 512, 256, 1, 1, 0, pmtot);
    bgemm(pk2, 256, ptw3,  88, k3b, pk3, RTOT, 256, CH,  0, 1, 0, pmtot);

    // masked neighbor reduce
    gno_reduce_k<<<NIN, 96>>>();

    // projection MLP
    bgemm(pgv, CH, ptwp, 256, p1b, pp1, NIN, CH, 256, 1, 1, 0);
    p2_k<<<NIN/8,256>>>(p2w, p2b, out);
}

// round 13
// speedup vs baseline: 1.4434x; 1.4434x over previous
#include <cuda_runtime.h>
#include <cuda_bf16.h>
#include <math.h>
#include <cstdint>

// ----------------------------------------------------------------------------
// FNO-GNO forward, sm_103. Round 13: revert GEMM to the round-10 engine
// (best: 4033us), plus fp64-free combine (stats finalized once).
// ----------------------------------------------------------------------------

#define S 54
#define S2 2916
#define S3 157464
#define CH 86
#define CS 13541904        // 86 * S3
#define NOUT 110592        // 48^3
#define NIN 8192
#define KNB 24
#define RTOT 196608        // NIN*KNB
#define MO 6
#define Q72 72
#define NMODE 864
#define WLAYER 6390144     // 4*216*86*86 (float2 per layer)
#define EPSGN 1e-5

// ---------------- device scratch ---------------------------------------------
__device__ float  g_h   [CS];
__device__ float  g_skip[CS];
__device__ float  g_hf  [CS];
__device__ float  g_t1  [CS];
__device__ float2 g_A1[CH*S2*MO];
__device__ float2 g_A2[CH*S*Q72];
__device__ float2 g_A3[CH*NMODE];
__device__ float2 g_M3[CH*NMODE];
__device__ float2 g_B2[CH*S*Q72];
__device__ float2 g_B1[CH*S2*MO];
__device__ float2 g_wp[4*WLAYER];
__device__ float  g_xoe[(size_t)NOUT*48];
__device__ float  g_xie[(size_t)NIN*48];
__device__ float  g_fy [(size_t)NOUT*CH];
__device__ float  g_y1 [(size_t)NOUT*512];
__device__ float  g_q1 [(size_t)NIN*512];
__device__ float  g_k1 [(size_t)RTOT*512];
__device__ float  g_k2 [(size_t)RTOT*256];
__device__ float  g_k3 [(size_t)RTOT*CH];
__device__ float  g_gv [(size_t)NIN*CH];
__device__ float  g_p1 [(size_t)NIN*256];
__device__ float  g_twy[48*512];
__device__ float  g_twq[48*512];
__device__ float  g_tw2[512*256];
__device__ float  g_tw3[256*88];
__device__ float  g_twp[86*256];
__device__ int    g_cnt [NIN];
__device__ int    g_base[NIN];
__device__ int    g_ci  [RTOT];
__device__ int    g_cnb [RTOT];
__device__ int    g_mtot[4];
__device__ double g_stats[2];
__device__ float  g_musw[2];            // finalized (mu, rs)
__device__ float  d_c12[648], d_s12[648];
__device__ int    g_mask_fmt;

__device__ __forceinline__ float gelu_f(float x){
    return 0.5f*x*(1.0f+erff(x*0.7071067811865476f));
}

// ---------------- bf16 mma helpers --------------------------------------------
__device__ __forceinline__ uint32_t pack_hi(float x0, float x1,
                                            float& r0, float& r1){
    __nv_bfloat16 h0 = __float2bfloat16(x0);
    __nv_bfloat16 h1 = __float2bfloat16(x1);
    r0 = x0 - __bfloat162float(h0);
    r1 = x1 - __bfloat162float(h1);
    __nv_bfloat162 t = __halves2bfloat162(h0, h1);
    return *(uint32_t*)&t;
}
__device__ __forceinline__ uint32_t pack_bf(float x0, float x1){
    __nv_bfloat162 t = __floats2bfloat162_rn(x0, x1);
    return *(uint32_t*)&t;
}
__device__ __forceinline__ void mma_bf16(float* c, const uint32_t* a, const uint32_t* b){
    asm volatile(
        "mma.sync.aligned.m16n8k16.row.col.f32.bf16.bf16.f32 "
        "{%0,%1,%2,%3}, {%4,%5,%6,%7}, {%8,%9}, {%0,%1,%2,%3};"
        : "+f"(c[0]),"+f"(c[1]),"+f"(c[2]),"+f"(c[3])
        : "r"(a[0]),"r"(a[1]),"r"(a[2]),"r"(a[3]), "r"(b[0]),"r"(b[1]));
}

// ---------------- mask dtype detection ---------------------------------------
__global__ void detect_mask_k(const unsigned char* __restrict__ m){
    __shared__ int s_f1, s_f3, s_nzna, s_oddw;
    if(threadIdx.x==0){ s_f1=0; s_f3=0; s_nzna=0; s_oddw=0; }
    __syncthreads();
    for(int i=threadIdx.x; i<4096; i+=blockDim.x){
        unsigned char b = m[i];
        int off = i & 3;
        if(b){
            if(off==1 && b==0x3F) atomicOr(&s_f1, 1);
            if(off==3 && b==0x3F) atomicOr(&s_f3, 1);
            if(off!=0)            atomicOr(&s_nzna, 1);
        }
    }
    const unsigned int* w = (const unsigned int*)m;
    for(int i=threadIdx.x; i<1024; i+=blockDim.x){
        if((i & 1) && w[i]) atomicOr(&s_oddw, 1);
    }
    __syncthreads();
    if(threadIdx.x==0){
        int fmt;
        if(s_f1)        fmt = 3;
        else if(s_f3)   fmt = 2;
        else if(s_nzna) fmt = 0;
        else if(s_oddw) fmt = 1;
        else            fmt = 4;
        g_mask_fmt = fmt;
    }
}
__device__ __forceinline__ int mask_at(const void* p, long r, int fmt){
    switch(fmt){
        case 0: return ((const unsigned char*)p)[r] != 0;
        case 1: return ((const int*)p)[r] != 0;
        case 2: return ((const float*)p)[r] != 0.f;
        case 3: return ((const unsigned short*)p)[r] != 0;
        default:return ((const long long*)p)[r] != 0;
    }
}

// ---------------- compaction ---------------------------------------------------
__global__ void count_k(const void* __restrict__ nb_mask){
    int i = blockIdx.x*256 + threadIdx.x;
    if(i >= NIN) return;
    int fmt = g_mask_fmt;
    int c = 0;
    for(int j=0;j<KNB;j++) c += mask_at(nb_mask, (long)i*KNB + j, fmt);
    g_cnt[i] = c;
}

__global__ void scan_k(){
    __shared__ int part[256];
    int t = threadIdx.x;
    int local[32];
    int s = 0;
    #pragma unroll
    for(int u=0;u<32;u++){
        local[u] = s;
        s += g_cnt[t*32 + u];
    }
    part[t] = s;
    __syncthreads();
    if(t == 0){
        int run = 0;
        for(int k=0;k<256;k++){ int v = part[k]; part[k] = run; run += v; }
        g_mtot[0] = run;
    }
    __syncthreads();
    int off = part[t];
    #pragma unroll
    for(int u=0;u<32;u++) g_base[t*32 + u] = off + local[u];
}

__global__ void fill_k(const int* __restrict__ nb_idx, const void* __restrict__ nb_mask){
    int i = blockIdx.x*256 + threadIdx.x;
    if(i >= NIN) return;
    int fmt = g_mask_fmt;
    int base = g_base[i], p = 0;
    for(int j=0;j<KNB;j++){
        if(mask_at(nb_mask, (long)i*KNB + j, fmt)){
            g_ci [base+p] = i;
            g_cnb[base+p] = nb_idx[i*KNB + j];
            p++;
        }
    }
}

// ---------------- prep -------------------------------------------------------
__global__ void basis_k(){
    int t = blockIdx.x*blockDim.x + threadIdx.x;
    if(t >= 648) return;
    int p = t/54, z = t%54;
    int ef = (p<6) ? p : (p+42);
    int m = (ef*z) % 54;
    double th = 6.283185307179586476925286766559 * (double)m / 54.0;
    d_c12[t] = (float)cos(th);
    d_s12[t] = (float)sin(th);
}
__global__ void zero_stats_k(){ g_stats[0]=0.0; g_stats[1]=0.0; }

// one thread: finalize (mu, rs) so combine_k is fp64-free
__global__ void finalize_stats_k(){
    double mu  = g_stats[0]/(double)CS;
    double var = g_stats[1]/(double)CS - mu*mu;
    g_musw[0] = (float)mu;
    g_musw[1] = (float)rsqrt(var + EPSGN);
}

__global__ void repack_k(const float* __restrict__ wr, const float* __restrict__ wi){
    long idx = (long)blockIdx.x*256 + threadIdx.x;
    if(idx >= 25560576L) return;
    long x = idx;
    int o = (int)(x%86); x/=86;
    int i = (int)(x%86); x/=86;
    int mloc = (int)(x%216); x/=216;
    long lb = x;
    long src = ((lb*86 + i)*86 + o)*216 + mloc;
    g_wp[idx] = make_float2(wr[src], wi[src]);
}

__global__ void transpose_k(const float* __restrict__ src, float* __restrict__ dst,
                            int O, int Kt, int Ktot, int k0, int ldd){
    int t = blockIdx.x*256 + threadIdx.x;
    if(t >= O*Kt) return;
    int k = t / O, o = t % O;
    dst[(size_t)k*ldd + o] = src[(size_t)o*Ktot + k0 + k];
}

// ---------------- lift --------------------------------------------------------
__global__ void lift_k(const float* __restrict__ df, const float* __restrict__ xout,
                       const float* __restrict__ w, const float* __restrict__ b){
    int n = blockIdx.x*256 + threadIdx.x;
    int c = blockIdx.y;
    if(n >= S3) return;
    int i = n/S2, j = (n/S)%S, k = n%S;
    float v = 0.f;
    if(i < 48 && j < 48 && k < 48){
        int n48 = (i*48 + j)*48 + k;
        float f0 = df[n48], f1 = df[NOUT + n48];
        float f2 = xout[n48*3+0], f3 = xout[n48*3+1], f4 = xout[n48*3+2];
        const float* wr = &w[c*5];
        v = b[c] + wr[0]*f0 + wr[1]*f1 + wr[2]*f2 + wr[3]*f3 + wr[4]*f4;
    }
    g_h[(size_t)c*S3 + n] = v;
}

// ---------------- bf16x3 tensor GEMM (round-10 engine) -------------------------
// C[M,N](ldc=N) = act( W[M,K](lda) @ X[K,N](ldx) + bias )
template<int BIASCOL, int ACT, int STATS>
__global__ __launch_bounds__(256, 2) void bgemm_k(
    const float* __restrict__ W, int lda,
    const float* __restrict__ X, int ldx,
    const float* __restrict__ Bv, float* __restrict__ C,
    int M, int K, int N, const int* __restrict__ Mdev)
{
    if(Mdev) M = *Mdev;
    const int bm = blockIdx.y*128, bn = blockIdx.x*128;
    if(bm >= M) return;
    __shared__ uint32_t aH[2][8][136], aL[2][8][136];
    __shared__ uint32_t bH[2][8][136], bL[2][8][136];
    const int tid = threadIdx.x;
    const int wid = tid>>5, lane = tid&31;
    const int gid = lane>>2, tig = lane&3;
    const int wm = (wid>>1)*32;
    const int wn = (wid&1)*64;

    float acc[2][8][4];
    #pragma unroll
    for(int a=0;a<2;a++)
        #pragma unroll
        for(int b=0;b<8;b++)
            #pragma unroll
            for(int c=0;c<4;c++) acc[a][b][c]=0.f;

    const int am   = tid & 127;
    const int akw0 = tid >> 7;
    const int bkw  = tid >> 5;
    const int bn4  = lane * 4;

    float  a0[4], a1[4];
    float4 bv0, bv1;

    auto loadT = [&](int kt){
        int k0 = kt*16;
        int gm = bm + am;
        #pragma unroll
        for(int u=0;u<4;u++){
            int gk = k0 + (akw0 + 2*u)*2;
            if(gm < M && gk+1 < K){
                float2 v = *(const float2*)&W[(size_t)gm*lda + gk];
                a0[u] = v.x; a1[u] = v.y;
            } else { a0[u]=0.f; a1[u]=0.f; }
        }
        int gk = k0 + bkw*2;
        int gn = bn + bn4;
        bv0 = make_float4(0.f,0.f,0.f,0.f);
        bv1 = make_float4(0.f,0.f,0.f,0.f);
        if(gn + 3 < N){
            if(gk   < K) bv0 = *(const float4*)&X[(size_t)gk*ldx + gn];
            if(gk+1 < K) bv1 = *(const float4*)&X[(size_t)(gk+1)*ldx + gn];
        } else {
            if(gk < K){
                if(gn+0<N) bv0.x = X[(size_t)gk*ldx + gn+0];
                if(gn+1<N) bv0.y = X[(size_t)gk*ldx + gn+1];
                if(gn+2<N) bv0.z = X[(size_t)gk*ldx + gn+2];
                if(gn+3<N) bv0.w = X[(size_t)gk*ldx + gn+3];
            }
            if(gk+1 < K){
                if(gn+0<N) bv1.x = X[(size_t)(gk+1)*ldx + gn+0];
                if(gn+1<N) bv1.y = X[(size_t)(gk+1)*ldx + gn+1];
                if(gn+2<N) bv1.z = X[(size_t)(gk+1)*ldx + gn+2];
                if(gn+3<N) bv1.w = X[(size_t)(gk+1)*ldx + gn+3];
            }
        }
    };
    auto storeT = [&](int b){
        #pragma unroll
        for(int u=0;u<4;u++){
            int kw = akw0 + 2*u;
            float l0,l1;
            aH[b][kw][am] = pack_hi(a0[u], a1[u], l0, l1);
            aL[b][kw][am] = pack_bf(l0, l1);
        }
        uint4 hw, lw;
        float l0,l1;
        hw.x = pack_hi(bv0.x, bv1.x, l0, l1); lw.x = pack_bf(l0, l1);
        hw.y = pack_hi(bv0.y, bv1.y, l0, l1); lw.y = pack_bf(l0, l1);
        hw.z = pack_hi(bv0.z, bv1.z, l0, l1); lw.z = pack_bf(l0, l1);
        hw.w = pack_hi(bv0.w, bv1.w, l0, l1); lw.w = pack_bf(l0, l1);
        *(uint4*)&bH[b][bkw][bn4] = hw;
        *(uint4*)&bL[b][bkw][bn4] = lw;
    };
    auto comp = [&](int b){
        uint32_t ah[2][4], al[2][4];
        #pragma unroll
        for(int mt=0; mt<2; mt++){
            int r0 = wm + mt*16 + gid;
            ah[mt][0]=aH[b][tig  ][r0];  ah[mt][1]=aH[b][tig  ][r0+8];
            ah[mt][2]=aH[b][4+tig][r0];  ah[mt][3]=aH[b][4+tig][r0+8];
            al[mt][0]=aL[b][tig  ][r0];  al[mt][1]=aL[b][tig  ][r0+8];
            al[mt][2]=aL[b][4+tig][r0];  al[mt][3]=aL[b][4+tig][r0+8];
        }
        #pragma unroll
        for(int nt=0; nt<8; nt++){
            int cn = wn + nt*8 + gid;
            uint32_t bh2[2], bl2[2];
            bh2[0]=bH[b][tig][cn]; bh2[1]=bH[b][4+tig][cn];
            bl2[0]=bL[b][tig][cn]; bl2[1]=bL[b][4+tig][cn];
            #pragma unroll
            for(int mt=0; mt<2; mt++){
                mma_bf16(acc[mt][nt], ah[mt], bh2);
                mma_bf16(acc[mt][nt], ah[mt], bl2);
                mma_bf16(acc[mt][nt], al[mt], bh2);
            }
        }
    };

    int ntiles = (K+15)>>4;
    loadT(0); storeT(0);
    __syncthreads();
    int buf = 0;
    for(int t=1; t<ntiles; t++){
        loadT(t);
        comp(buf);
        storeT(buf^1);
        __syncthreads();
        buf ^= 1;
    }
    comp(buf);

    float ssum = 0.f, ssq = 0.f;
    #pragma unroll
    for(int mt=0; mt<2; mt++){
        int r0 = bm + wm + mt*16 + gid;
        int r1 = r0 + 8;
        float rb0 = 0.f, rb1 = 0.f;
        if(!BIASCOL && Bv){
            if(r0 < M) rb0 = Bv[r0];
            if(r1 < M) rb1 = Bv[r1];
        }
        #pragma unroll
        for(int nt=0; nt<8; nt++){
            int gn = bn + wn + nt*8 + tig*2;
            float cb0 = 0.f, cb1 = 0.f;
            if(BIASCOL && Bv){
                if(gn   < N) cb0 = Bv[gn];
                if(gn+1 < N) cb1 = Bv[gn+1];
            }
            float v0 = acc[mt][nt][0] + (BIASCOL ? cb0 : rb0);
            float v1 = acc[mt][nt][1] + (BIASCOL ? cb1 : rb0);
            float v2 = acc[mt][nt][2] + (BIASCOL ? cb0 : rb1);
            float v3 = acc[mt][nt][3] + (BIASCOL ? cb1 : rb1);
            if(ACT){ v0=gelu_f(v0); v1=gelu_f(v1); v2=gelu_f(v2); v3=gelu_f(v3); }
            if(r0 < M){
                if(gn   < N){ C[(size_t)r0*N + gn]   = v0; if(STATS){ ssum+=v0; ssq=fmaf(v0,v0,ssq);} }
                if(gn+1 < N){ C[(size_t)r0*N + gn+1] = v1; if(STATS){ ssum+=v1; ssq=fmaf(v1,v1,ssq);} }
            }
            if(r1 < M){
                if(gn   < N){ C[(size_t)r1*N + gn]   = v2; if(STATS){ ssum+=v2; ssq=fmaf(v2,v2,ssq);} }
                if(gn+1 < N){ C[(size_t)r1*N + gn+1] = v3; if(STATS){ ssum+=v3; ssq=fmaf(v3,v3,ssq);} }
            }
        }
    }
    if(STATS){
        #pragma unroll
        for(int o=16;o>0;o>>=1){
            ssum += __shfl_down_sync(0xffffffffu, ssum, o);
            ssq  += __shfl_down_sync(0xffffffffu, ssq,  o);
        }
        __shared__ double ds[8], ds2[8];
        if(lane==0){ ds[wid]=(double)ssum; ds2[wid]=(double)ssq; }
        __syncthreads();
        if(tid==0){
            double a=0,b=0;
            #pragma unroll
            for(int k=0;k<8;k++){ a+=ds[k]; b+=ds2[k]; }
            atomicAdd(&g_stats[0], a);
            atomicAdd(&g_stats[1], b);
        }
    }
}

// ---------------- partial DFT chain (col-major h) ------------------------------
__global__ void dft_z_k(const float* __restrict__ h){
    __shared__ float sh[32*54];
    __shared__ float bc[324], bs[324];
    int t = threadIdx.x;                // 192
    long rowbase = (long)blockIdx.x*32;
    for(int i=t;i<324;i+=192){ bc[i]=d_c12[i]; bs[i]=d_s12[i]; }
    long gbase = rowbase*54;
    const long TOT = (long)CH*S2*54;
    for(int i=t;i<32*54;i+=192){
        long g = gbase + i;
        sh[i] = (g < TOT) ? h[g] : 0.f;
    }
    __syncthreads();
    int r = t/6, kz = t%6;
    long row = rowbase + r;
    if(row < (long)CH*S2){
        float re=0.f, im=0.f;
        const float* x = &sh[r*54];
        #pragma unroll
        for(int z=0;z<54;z++){
            float v = x[z];
            re = fmaf(v, bc[kz*54+z], re);
            im = fmaf(-v, bs[kz*54+z], im);
        }
        g_A1[row*6+kz] = make_float2(re, im);
    }
}

__global__ void dft_y_k(){
    __shared__ float2 sh[324];
    int t = threadIdx.x;                // 128
    int cx = blockIdx.x;
    const float2* src = g_A1 + (size_t)cx*324;
    for(int i=t;i<324;i+=128) sh[i] = src[i];
    __syncthreads();
    if(t < 72){
        int ky = t/6, kz = t%6;
        float re=0.f, im=0.f;
        for(int y=0;y<54;y++){
            float2 v = sh[y*6+kz];
            float c = d_c12[ky*54+y], s = d_s12[ky*54+y];
            re += v.x*c + v.y*s;
            im += v.y*c - v.x*s;
        }
        g_A2[(size_t)cx*72 + t] = make_float2(re, im);
    }
}

__global__ void dft_x_k(){
    __shared__ float2 sh[S*Q72];
    int t = threadIdx.x;                // 256
    int c = blockIdx.x;
    const float2* src = g_A2 + (size_t)c*(S*Q72);
    for(int i=t;i<S*Q72;i+=256) sh[i] = src[i];
    __syncthreads();
    for(int u=t; u<NMODE; u+=256){
        int kx = u/72, q = u%72;
        float re=0.f, im=0.f;
        for(int x=0;x<54;x++){
            float2 v = sh[x*72+q];
            float cc = d_c12[kx*54+x], s = d_s12[kx*54+x];
            re += v.x*cc + v.y*s;
            im += v.y*cc - v.x*s;
        }
        g_A3[(size_t)c*NMODE + u] = make_float2(re, im);
    }
}

__global__ void mix_k(const float2* __restrict__ wp){
    __shared__ float2 a[86];
    int m = blockIdx.x;                 // 864
    int t = threadIdx.x;                // 96
    int kx = m/72, ky = (m%72)/6, kz = m%6;
    if(t < 86) a[t] = g_A3[(size_t)t*NMODE + m];
    __syncthreads();
    if(t < 86){
        int cblk = (kx>=6)*2 + (ky>=6);
        int mloc = (kx%6)*36 + (ky%6)*6 + kz;
        const float2* w = wp + ((size_t)cblk*216 + mloc)*7396 + t;
        float re=0.f, im=0.f;
        for(int i=0;i<86;i++){
            float2 av = a[i];
            float2 wv = w[(size_t)i*86];
            re += av.x*wv.x - av.y*wv.y;
            im += av.x*wv.y + av.y*wv.x;
        }
        g_M3[(size_t)t*NMODE + m] = make_float2(re, im);
    }
}

__global__ void inv_x_k(){
    __shared__ float2 sh[NMODE];
    int t = threadIdx.x;                // 256
    int c = blockIdx.x;
    for(int i=t;i<NMODE;i+=256) sh[i] = g_M3[(size_t)c*NMODE + i];
    __syncthreads();
    for(int u=t; u<S*Q72; u+=256){
        int x = u/72, q = u%72;
        float re=0.f, im=0.f;
        #pragma unroll
        for(int p=0;p<12;p++){
            float2 v = sh[p*72+q];
            float cc = d_c12[p*54+x], s = d_s12[p*54+x];
            re += v.x*cc - v.y*s;
            im += v.x*s  + v.y*cc;
        }
        g_B2[(size_t)c*(S*Q72) + u] = make_float2(re, im);
    }
}

__global__ void inv_y_k(){
    __shared__ float2 sh[72];
    int t = threadIdx.x;                // 128
    int cx = blockIdx.x;
    if(t < 72) sh[t] = g_B2[(size_t)cx*72 + t];
    __syncthreads();
    for(int u=t; u<324; u+=128){
        int y = u/6, kz = u%6;
        float re=0.f, im=0.f;
        #pragma unroll
        for(int ky=0;ky<12;ky++){
            float2 v = sh[ky*6+kz];
            float cc = d_c12[ky*54+y], s = d_s12[ky*54+y];
            re += v.x*cc - v.y*s;
            im += v.x*s  + v.y*cc;
        }
        g_B1[(size_t)cx*324 + u] = make_float2(re, im);
    }
}

// inv-z with fused stats accumulation
__global__ void inv_z_k(){
    __shared__ float2 sh[324];
    int t = threadIdx.x;                // 256
    int cx = blockIdx.x;
    for(int i=t;i<324;i+=256) sh[i] = g_B1[(size_t)cx*324 + i];
    __syncthreads();
    const float inv = 1.0f/157464.0f;
    float ssum=0.f, ssq=0.f;
    for(int u=t; u<S2; u+=256){
        int y = u/54, z = u%54;
        const float2* b = &sh[y*6];
        float v = b[0].x;
        #pragma unroll
        for(int kz=1;kz<6;kz++){
            float cc = d_c12[kz*54+z], s = d_s12[kz*54+z];
            v += 2.f*(b[kz].x*cc - b[kz].y*s);
        }
        v *= inv;
        g_hf[(size_t)cx*S2 + u] = v;
        ssum += v; ssq = fmaf(v,v,ssq);
    }
    #pragma unroll
    for(int o=16;o>0;o>>=1){
        ssum += __shfl_down_sync(0xffffffffu, ssum, o);
        ssq  += __shfl_down_sync(0xffffffffu, ssq,  o);
    }
    __shared__ double ds[8], ds2[8];
    int w = t>>5;
    if((t&31)==0){ ds[w]=(double)ssum; ds2[w]=(double)ssq; }
    __syncthreads();
    if(t==0){
        double a=0,b=0;
        #pragma unroll
        for(int k=0;k<8;k++){ a+=ds[k]; b+=ds2[k]; }
        atomicAdd(&g_stats[0], a);
        atomicAdd(&g_stats[1], b);
    }
}

// ---------------- combine (fp64-free) ------------------------------------------
__global__ void combine_k(const float4* __restrict__ buf, const float4* __restrict__ add,
                          const float* __restrict__ gw, const float* __restrict__ gb,
                          float4* __restrict__ h, int actflag){
    long i = (long)blockIdx.x*blockDim.x + threadIdx.x;
    if(i >= (CS>>2)) return;
    float fmu = g_musw[0];
    float rs  = g_musw[1];
    int c = (int)((i<<2) / S3);
    float sw = rs*gw[c], sb = gb[c];
    float4 u = buf[i], a = add[i];
    float4 o;
    o.x = (u.x-fmu)*sw + sb + a.x;
    o.y = (u.y-fmu)*sw + sb + a.y;
    o.z = (u.z-fmu)*sw + sb + a.z;
    o.w = (u.w-fmu)*sw + sb + a.w;
    if(actflag){ o.x=gelu_f(o.x); o.y=gelu_f(o.y); o.z=gelu_f(o.z); o.w=gelu_f(o.w); }
    h[i] = o;
}

// ---------------- GNO head (row-major, compacted) ------------------------------
__global__ void embed_k(const float* __restrict__ pts, float* __restrict__ out, int n){
    int i = blockIdx.x*blockDim.x + threadIdx.x;
    if(i >= n) return;
    #pragma unroll
    for(int d=0; d<3; d++){
        float x = pts[i*3+d];
        #pragma unroll
        for(int f=0; f<8; f++){
            float fr = powf(1e-4f, (float)f/8.0f);
            float a = x*fr;
            out[(size_t)i*48 + d*16 + f]     = cosf(a);
            out[(size_t)i*48 + d*16 + 8 + f] = sinf(a);
        }
    }
}

__global__ void crop_k(){
    int n = blockIdx.x*256 + threadIdx.x;
    int c = blockIdx.y;
    if(n >= NOUT) return;
    int i = n/2304, j = (n/48)%48, k = n%48;
    g_fy[(size_t)n*CH + c] = g_h[((size_t)(c*S + i)*S + j)*S + k];
}

__global__ void k1_fuse_k(){
    long gt = (long)blockIdx.x*256 + threadIdx.x;
    int s  = (int)(gt >> 7);
    if(s >= g_mtot[0]) return;
    int c4 = ((int)gt & 127) << 2;
    int idx = g_cnb[s];
    int i = g_ci[s];
    float4 y = *(const float4*)&g_y1[(size_t)idx*512 + c4];
    float4 q = *(const float4*)&g_q1[(size_t)i*512 + c4];
    float4 o;
    o.x = gelu_f(y.x+q.x); o.y = gelu_f(y.y+q.y);
    o.z = gelu_f(y.z+q.z); o.w = gelu_f(y.w+q.w);
    *(float4*)&g_k1[(size_t)s*512 + c4] = o;
}

__global__ void gno_reduce_k(){
    int i = blockIdx.x;                 // NIN
    int c = threadIdx.x;                // 96 (86 active)
    __shared__ int sidx[KNB];
    __shared__ int sbase, scnt;
    if(c == 0){ sbase = g_base[i]; scnt = g_cnt[i]; }
    __syncthreads();
    if(c < scnt) sidx[c] = g_cnb[sbase + c];
    __syncthreads();
    if(c >= CH) return;
    float acc = 0.f;
    int cnt = scnt;
    for(int j=0; j<cnt; j++){
        acc += g_k3[((size_t)(sbase+j))*CH + c] * g_fy[(size_t)sidx[j]*CH + c];
    }
    float den = (float)(cnt > 1 ? cnt : 1);
    g_gv[(size_t)i*CH + c] = acc/den;
}

__global__ void p2_k(const float* __restrict__ w, const float* __restrict__ b,
                     float* __restrict__ out){
    int warp = threadIdx.x>>5, lane = threadIdx.x&31;
    int row = blockIdx.x*8 + warp;
    if(row >= NIN) return;
    const float* pr = g_p1 + (size_t)row*256;
    float acc = 0.f;
    #pragma unroll
    for(int f=lane; f<256; f+=32) acc = fmaf(w[f], pr[f], acc);
    #pragma unroll
    for(int o=16;o>0;o>>=1) acc += __shfl_down_sync(0xffffffffu, acc, o);
    if(lane==0) out[row] = acc + b[0];
}

// ---------------- host orchestration -----------------------------------------
static void bgemm(const float* W, int lda, const float* X, int ldx,
                  const float* B, float* C,
                  int M, int K, int N, int act, int biascol, int stats,
                  const int* Mdev = 0){
    dim3 grid((N+127)/128, (M+127)/128);
    if(biascol){
        if(act) bgemm_k<1,1,0><<<grid,256>>>(W,lda,X,ldx,B,C,M,K,N,Mdev);
        else    bgemm_k<1,0,0><<<grid,256>>>(W,lda,X,ldx,B,C,M,K,N,Mdev);
    } else if(stats){
        bgemm_k<0,0,1><<<grid,256>>>(W,lda,X,ldx,B,C,M,K,N,Mdev);
    } else {
        if(act) bgemm_k<0,1,0><<<grid,256>>>(W,lda,X,ldx,B,C,M,K,N,Mdev);
        else    bgemm_k<0,0,0><<<grid,256>>>(W,lda,X,ldx,B,C,M,K,N,Mdev);
    }
}

extern "C" void kernel_launch(void* const* d_in, const int* in_sizes, int n_in,
                              void* d_out, int out_size){
    const float* x_in   = (const float*)d_in[0];
    const float* x_out  = (const float*)d_in[1];
    const float* df     = (const float*)d_in[2];
    const int*   nb_idx = (const int*)  d_in[3];
    const void*  nb_mask= (const void*) d_in[4];
    const float* w_lift = (const float*)d_in[5];
    const float* b_lift = (const float*)d_in[6];
    const float* spec_wr= (const float*)d_in[7];
    const float* spec_wi= (const float*)d_in[8];
    const float* w_skip = (const float*)d_in[9];
    const float* b_skip = (const float*)d_in[10];
    const float* mlp1_w = (const float*)d_in[11];
    const float* mlp1_b = (const float*)d_in[12];
    const float* mlp2_w = (const float*)d_in[13];
    const float* mlp2_b = (const float*)d_in[14];
    const float* wms    = (const float*)d_in[15];
    const float* bms    = (const float*)d_in[16];
    const float* g1w    = (const float*)d_in[17];
    const float* g1b    = (const float*)d_in[18];
    const float* g2w    = (const float*)d_in[19];
    const float* g2b    = (const float*)d_in[20];
    const float* k1w    = (const float*)d_in[21];
    const float* k1b    = (const float*)d_in[22];
    const float* k2w    = (const float*)d_in[23];
    const float* k2b    = (const float*)d_in[24];
    const float* k3w    = (const float*)d_in[25];
    const float* k3b    = (const float*)d_in[26];
    const float* p1w    = (const float*)d_in[27];
    const float* p1b    = (const float*)d_in[28];
    const float* p2w    = (const float*)d_in[29];
    const float* p2b    = (const float*)d_in[30];
    float* out = (float*)d_out;

    float *ph, *pskip, *phf, *pt1, *pxoe, *pxie, *py1, *pq1, *pk1, *pk2, *pk3, *pgv, *pp1;
    float *ptwy, *ptwq, *ptw2, *ptw3, *ptwp;
    float2 *pwp;
    int *pmtot;
    cudaGetSymbolAddress((void**)&ph,    g_h);
    cudaGetSymbolAddress((void**)&pskip, g_skip);
    cudaGetSymbolAddress((void**)&phf,   g_hf);
    cudaGetSymbolAddress((void**)&pt1,   g_t1);
    cudaGetSymbolAddress((void**)&pxoe,  g_xoe);
    cudaGetSymbolAddress((void**)&pxie,  g_xie);
    cudaGetSymbolAddress((void**)&py1,   g_y1);
    cudaGetSymbolAddress((void**)&pq1,   g_q1);
    cudaGetSymbolAddress((void**)&pk1,   g_k1);
    cudaGetSymbolAddress((void**)&pk2,   g_k2);
    cudaGetSymbolAddress((void**)&pk3,   g_k3);
    cudaGetSymbolAddress((void**)&pgv,   g_gv);
    cudaGetSymbolAddress((void**)&pp1,   g_p1);
    cudaGetSymbolAddress((void**)&ptwy,  g_twy);
    cudaGetSymbolAddress((void**)&ptwq,  g_twq);
    cudaGetSymbolAddress((void**)&ptw2,  g_tw2);
    cudaGetSymbolAddress((void**)&ptw3,  g_tw3);
    cudaGetSymbolAddress((void**)&ptwp,  g_twp);
    cudaGetSymbolAddress((void**)&pwp,   g_wp);
    cudaGetSymbolAddress((void**)&pmtot, g_mtot);

    // prep
    basis_k<<<2,384>>>();
    detect_mask_k<<<1,256>>>((const unsigned char*)nb_mask);
    count_k<<<NIN/256,256>>>(nb_mask);
    scan_k<<<1,256>>>();
    fill_k<<<NIN/256,256>>>(nb_idx, nb_mask);
    {
        dim3 g((S3+255)/256, CH);
        lift_k<<<g,256>>>(df, x_out, w_lift, b_lift);
    }
    bgemm(w_skip, CH, ph, S3, b_skip, pskip, CH, CH, S3, 0, 0, 0);
    repack_k<<<(int)((25560576L+255)/256),256>>>(spec_wr, spec_wi);
    transpose_k<<<(512*48 +255)/256,256>>>(k1w, ptwy, 512,  48,  96, 0,  512);
    transpose_k<<<(512*48 +255)/256,256>>>(k1w, ptwq, 512,  48,  96, 48, 512);
    transpose_k<<<(256*512+255)/256,256>>>(k2w, ptw2, 256, 512, 512, 0,  256);
    transpose_k<<<(86*256 +255)/256,256>>>(k3w, ptw3,  86, 256, 256, 0,   88);
    transpose_k<<<(256*86 +255)/256,256>>>(p1w, ptwp, 256,  86,  86, 0,  256);

    // FNO layers
    for(int l=0;l<4;l++){
        int act = (l<3) ? 1 : 0;
        if(l > 0)
            bgemm(w_skip + (size_t)l*CH*CH, CH, ph, S3, b_skip + l*CH, pskip, CH, CH, S3, 0, 0, 0);
        dft_z_k<<<(CH*S2+31)/32, 192>>>(ph);
        dft_y_k<<<CH*S, 128>>>();
        dft_x_k<<<CH, 256>>>();
        mix_k<<<NMODE, 96>>>(pwp + (size_t)l*WLAYER);
        inv_x_k<<<CH, 256>>>();
        inv_y_k<<<CH*S, 128>>>();
        zero_stats_k<<<1,1>>>();
        inv_z_k<<<CH*S, 256>>>();
        finalize_stats_k<<<1,1>>>();
        combine_k<<<((CS>>2)+255)/256,256>>>((const float4*)phf,(const float4*)pskip,
                                             g1w + l*CH, g1b + l*CH, (float4*)ph, act);
        bgemm(wms    + (size_t)l*CH*CH, CH, ph,  S3, bms    + l*CH, pskip, CH, CH, S3, 0, 0, 0);
        bgemm(mlp1_w + (size_t)l*CH*CH, CH, ph,  S3, mlp1_b + l*CH, pt1,   CH, CH, S3, 1, 0, 0);
        zero_stats_k<<<1,1>>>();
        bgemm(mlp2_w + (size_t)l*CH*CH, CH, pt1, S3, mlp2_b + l*CH, phf,   CH, CH, S3, 0, 0, 1);
        finalize_stats_k<<<1,1>>>();
        combine_k<<<((CS>>2)+255)/256,256>>>((const float4*)phf,(const float4*)pskip,
                                             g2w + l*CH, g2b + l*CH, (float4*)ph, act);
    }

    // crop f_y
    {
        dim3 g((NOUT+255)/256, CH);
        crop_k<<<g,256>>>();
    }

    // row-major embeddings
    embed_k<<<(NOUT+127)/128,128>>>(x_out, pxoe, NOUT);
    embed_k<<<(NIN +127)/128,128>>>(x_in,  pxie, NIN);

    // GNO kernel MLP on compacted rows
    bgemm(pxoe, 48, ptwy, 512, 0,   py1, NOUT, 48, 512, 0, 1, 0);
    bgemm(pxie, 48, ptwq, 512, k1b, pq1, NIN,  48, 512, 0, 1, 0);
    k1_fuse_k<<<(int)(((long)RTOT*128)/256),256>>>();
    bgemm(pk1, 512, ptw2, 256, k2b, pk2, RTOT, 512, 256, 1, 1, 0, pmtot);
    bgemm(pk2, 256, ptw3,  88, k3b, pk3, RTOT, 256, CH,  0, 1, 0, pmtot);

    // masked neighbor reduce
    gno_reduce_k<<<NIN, 96>>>();

    // projection MLP
    bgemm(pgv, CH, ptwp, 256, p1b, pp1, NIN, CH, 256, 1, 1, 0);
    p2_k<<<NIN/8,256>>>(p2w, p2b, out);
}

// round 14
// speedup vs baseline: 1.4526x; 1.0063x over previous
#include <cuda_runtime.h>
#include <cuda_bf16.h>
#include <math.h>
#include <cstdint>

// ----------------------------------------------------------------------------
// FNO-GNO forward, sm_103. Round 14: round-13 (best 3018us) + dual-output
// mskip/mlp1 GEMM (stacked M=172) + stats zero folded into finalize.
// ----------------------------------------------------------------------------

#define S 54
#define S2 2916
#define S3 157464
#define CH 86
#define CS 13541904        // 86 * S3
#define NOUT 110592        // 48^3
#define NIN 8192
#define KNB 24
#define RTOT 196608        // NIN*KNB
#define MO 6
#define Q72 72
#define NMODE 864
#define WLAYER 6390144     // 4*216*86*86 (float2 per layer)
#define EPSGN 1e-5
#define MDUAL 172          // 2*CH stacked rows

// ---------------- device scratch ---------------------------------------------
__device__ float  g_h   [CS];
__device__ float  g_skip[CS];
__device__ float  g_hf  [CS];
__device__ float  g_t1  [CS];
__device__ float2 g_A1[CH*S2*MO];
__device__ float2 g_A2[CH*S*Q72];
__device__ float2 g_A3[CH*NMODE];
__device__ float2 g_M3[CH*NMODE];
__device__ float2 g_B2[CH*S*Q72];
__device__ float2 g_B1[CH*S2*MO];
__device__ float2 g_wp[4*WLAYER];
__device__ float  g_xoe[(size_t)NOUT*48];
__device__ float  g_xie[(size_t)NIN*48];
__device__ float  g_fy [(size_t)NOUT*CH];
__device__ float  g_y1 [(size_t)NOUT*512];
__device__ float  g_q1 [(size_t)NIN*512];
__device__ float  g_k1 [(size_t)RTOT*512];
__device__ float  g_k2 [(size_t)RTOT*256];
__device__ float  g_k3 [(size_t)RTOT*CH];
__device__ float  g_gv [(size_t)NIN*CH];
__device__ float  g_p1 [(size_t)NIN*256];
__device__ float  g_twy[48*512];
__device__ float  g_twq[48*512];
__device__ float  g_tw2[512*256];
__device__ float  g_tw3[256*88];
__device__ float  g_twp[86*256];
__device__ float  g_wd [4*MDUAL*CH];        // stacked [wms; mlp1_w] per layer
__device__ float  g_bd [4*MDUAL];           // stacked [bms; mlp1_b] per layer
__device__ int    g_cnt [NIN];
__device__ int    g_base[NIN];
__device__ int    g_ci  [RTOT];
__device__ int    g_cnb [RTOT];
__device__ int    g_mtot[4];
__device__ double g_stats[2];
__device__ float  g_musw[2];                // finalized (mu, rs)
__device__ float  d_c12[648], d_s12[648];
__device__ int    g_mask_fmt;

__device__ __forceinline__ float gelu_f(float x){
    return 0.5f*x*(1.0f+erff(x*0.7071067811865476f));
}

// ---------------- bf16 mma helpers --------------------------------------------
__device__ __forceinline__ uint32_t pack_hi(float x0, float x1,
                                            float& r0, float& r1){
    __nv_bfloat16 h0 = __float2bfloat16(x0);
    __nv_bfloat16 h1 = __float2bfloat16(x1);
    r0 = x0 - __bfloat162float(h0);
    r1 = x1 - __bfloat162float(h1);
    __nv_bfloat162 t = __halves2bfloat162(h0, h1);
    return *(uint32_t*)&t;
}
__device__ __forceinline__ uint32_t pack_bf(float x0, float x1){
    __nv_bfloat162 t = __floats2bfloat162_rn(x0, x1);
    return *(uint32_t*)&t;
}
__device__ __forceinline__ void mma_bf16(float* c, const uint32_t* a, const uint32_t* b){
    asm volatile(
        "mma.sync.aligned.m16n8k16.row.col.f32.bf16.bf16.f32 "
        "{%0,%1,%2,%3}, {%4,%5,%6,%7}, {%8,%9}, {%0,%1,%2,%3};"
        : "+f"(c[0]),"+f"(c[1]),"+f"(c[2]),"+f"(c[3])
        : "r"(a[0]),"r"(a[1]),"r"(a[2]),"r"(a[3]), "r"(b[0]),"r"(b[1]));
}

// ---------------- mask dtype detection ---------------------------------------
__global__ void detect_mask_k(const unsigned char* __restrict__ m){
    __shared__ int s_f1, s_f3, s_nzna, s_oddw;
    if(threadIdx.x==0){ s_f1=0; s_f3=0; s_nzna=0; s_oddw=0; }
    __syncthreads();
    for(int i=threadIdx.x; i<4096; i+=blockDim.x){
        unsigned char b = m[i];
        int off = i & 3;
        if(b){
            if(off==1 && b==0x3F) atomicOr(&s_f1, 1);
            if(off==3 && b==0x3F) atomicOr(&s_f3, 1);
            if(off!=0)            atomicOr(&s_nzna, 1);
        }
    }
    const unsigned int* w = (const unsigned int*)m;
    for(int i=threadIdx.x; i<1024; i+=blockDim.x){
        if((i & 1) && w[i]) atomicOr(&s_oddw, 1);
    }
    __syncthreads();
    if(threadIdx.x==0){
        int fmt;
        if(s_f1)        fmt = 3;
        else if(s_f3)   fmt = 2;
        else if(s_nzna) fmt = 0;
        else if(s_oddw) fmt = 1;
        else            fmt = 4;
        g_mask_fmt = fmt;
    }
}
__device__ __forceinline__ int mask_at(const void* p, long r, int fmt){
    switch(fmt){
        case 0: return ((const unsigned char*)p)[r] != 0;
        case 1: return ((const int*)p)[r] != 0;
        case 2: return ((const float*)p)[r] != 0.f;
        case 3: return ((const unsigned short*)p)[r] != 0;
        default:return ((const long long*)p)[r] != 0;
    }
}

// ---------------- compaction ---------------------------------------------------
__global__ void count_k(const void* __restrict__ nb_mask){
    int i = blockIdx.x*256 + threadIdx.x;
    if(i >= NIN) return;
    int fmt = g_mask_fmt;
    int c = 0;
    for(int j=0;j<KNB;j++) c += mask_at(nb_mask, (long)i*KNB + j, fmt);
    g_cnt[i] = c;
}

__global__ void scan_k(){
    __shared__ int part[256];
    int t = threadIdx.x;
    int local[32];
    int s = 0;
    #pragma unroll
    for(int u=0;u<32;u++){
        local[u] = s;
        s += g_cnt[t*32 + u];
    }
    part[t] = s;
    __syncthreads();
    if(t == 0){
        int run = 0;
        for(int k=0;k<256;k++){ int v = part[k]; part[k] = run; run += v; }
        g_mtot[0] = run;
    }
    __syncthreads();
    int off = part[t];
    #pragma unroll
    for(int u=0;u<32;u++) g_base[t*32 + u] = off + local[u];
}

__global__ void fill_k(const int* __restrict__ nb_idx, const void* __restrict__ nb_mask){
    int i = blockIdx.x*256 + threadIdx.x;
    if(i >= NIN) return;
    int fmt = g_mask_fmt;
    int base = g_base[i], p = 0;
    for(int j=0;j<KNB;j++){
        if(mask_at(nb_mask, (long)i*KNB + j, fmt)){
            g_ci [base+p] = i;
            g_cnb[base+p] = nb_idx[i*KNB + j];
            p++;
        }
    }
}

// ---------------- prep -------------------------------------------------------
__global__ void basis_k(){
    int t = blockIdx.x*blockDim.x + threadIdx.x;
    if(t >= 648) return;
    int p = t/54, z = t%54;
    int ef = (p<6) ? p : (p+42);
    int m = (ef*z) % 54;
    double th = 6.283185307179586476925286766559 * (double)m / 54.0;
    d_c12[t] = (float)cos(th);
    d_s12[t] = (float)sin(th);
}
__global__ void zero_stats_k(){ g_stats[0]=0.0; g_stats[1]=0.0; }

// finalize (mu, rs), then reset accumulators for the next pass
__global__ void finalize_stats_k(){
    double mu  = g_stats[0]/(double)CS;
    double var = g_stats[1]/(double)CS - mu*mu;
    g_musw[0] = (float)mu;
    g_musw[1] = (float)rsqrt(var + EPSGN);
    g_stats[0] = 0.0;
    g_stats[1] = 0.0;
}

__global__ void repack_k(const float* __restrict__ wr, const float* __restrict__ wi){
    long idx = (long)blockIdx.x*256 + threadIdx.x;
    if(idx >= 25560576L) return;
    long x = idx;
    int o = (int)(x%86); x/=86;
    int i = (int)(x%86); x/=86;
    int mloc = (int)(x%216); x/=216;
    long lb = x;
    long src = ((lb*86 + i)*86 + o)*216 + mloc;
    g_wp[idx] = make_float2(wr[src], wi[src]);
}

__global__ void transpose_k(const float* __restrict__ src, float* __restrict__ dst,
                            int O, int Kt, int Ktot, int k0, int ldd){
    int t = blockIdx.x*256 + threadIdx.x;
    if(t >= O*Kt) return;
    int k = t / O, o = t % O;
    dst[(size_t)k*ldd + o] = src[(size_t)o*Ktot + k0 + k];
}

// stack [wms; mlp1_w] and [bms; mlp1_b] per layer
__global__ void stack_k(const float* __restrict__ wms, const float* __restrict__ mlp1w,
                        const float* __restrict__ bms, const float* __restrict__ mlp1b){
    int t = blockIdx.x*256 + threadIdx.x;
    int per = MDUAL*CH;
    if(t < 4*per){
        int l = t / per, r = (t % per) / CH, c = t % CH;
        float v = (r < CH) ? wms[((size_t)l*CH + r)*CH + c]
                           : mlp1w[((size_t)l*CH + (r-CH))*CH + c];
        g_wd[t] = v;
    }
    if(t < 4*MDUAL){
        int l = t / MDUAL, r = t % MDUAL;
        g_bd[t] = (r < CH) ? bms[l*CH + r] : mlp1b[l*CH + (r-CH)];
    }
}

// ---------------- lift --------------------------------------------------------
__global__ void lift_k(const float* __restrict__ df, const float* __restrict__ xout,
                       const float* __restrict__ w, const float* __restrict__ b){
    int n = blockIdx.x*256 + threadIdx.x;
    int c = blockIdx.y;
    if(n >= S3) return;
    int i = n/S2, j = (n/S)%S, k = n%S;
    float v = 0.f;
    if(i < 48 && j < 48 && k < 48){
        int n48 = (i*48 + j)*48 + k;
        float f0 = df[n48], f1 = df[NOUT + n48];
        float f2 = xout[n48*3+0], f3 = xout[n48*3+1], f4 = xout[n48*3+2];
        const float* wr = &w[c*5];
        v = b[c] + wr[0]*f0 + wr[1]*f1 + wr[2]*f2 + wr[3]*f3 + wr[4]*f4;
    }
    g_h[(size_t)c*S3 + n] = v;
}

// ---------------- bf16x3 tensor GEMM (round-10 engine) -------------------------
// DUAL=1: rows < CH -> C (no act), rows >= CH -> C2 at (r-CH) with GELU.
template<int BIASCOL, int ACT, int STATS, int DUAL>
__global__ __launch_bounds__(256, 2) void bgemm_k(
    const float* __restrict__ W, int lda,
    const float* __restrict__ X, int ldx,
    const float* __restrict__ Bv, float* __restrict__ C,
    float* __restrict__ C2,
    int M, int K, int N, const int* __restrict__ Mdev)
{
    if(Mdev) M = *Mdev;
    const int bm = blockIdx.y*128, bn = blockIdx.x*128;
    if(bm >= M) return;
    __shared__ uint32_t aH[2][8][136], aL[2][8][136];
    __shared__ uint32_t bH[2][8][136], bL[2][8][136];
    const int tid = threadIdx.x;
    const int wid = tid>>5, lane = tid&31;
    const int gid = lane>>2, tig = lane&3;
    const int wm = (wid>>1)*32;
    const int wn = (wid&1)*64;

    float acc[2][8][4];
    #pragma unroll
    for(int a=0;a<2;a++)
        #pragma unroll
        for(int b=0;b<8;b++)
            #pragma unroll
            for(int c=0;c<4;c++) acc[a][b][c]=0.f;

    const int am   = tid & 127;
    const int akw0 = tid >> 7;
    const int bkw  = tid >> 5;
    const int bn4  = lane * 4;

    float  a0[4], a1[4];
    float4 bv0, bv1;

    auto loadT = [&](int kt){
        int k0 = kt*16;
        int gm = bm + am;
        #pragma unroll
        for(int u=0;u<4;u++){
            int gk = k0 + (akw0 + 2*u)*2;
            if(gm < M && gk+1 < K){
                float2 v = *(const float2*)&W[(size_t)gm*lda + gk];
                a0[u] = v.x; a1[u] = v.y;
            } else { a0[u]=0.f; a1[u]=0.f; }
        }
        int gk = k0 + bkw*2;
        int gn = bn + bn4;
        bv0 = make_float4(0.f,0.f,0.f,0.f);
        bv1 = make_float4(0.f,0.f,0.f,0.f);
        if(gn + 3 < N){
            if(gk   < K) bv0 = *(const float4*)&X[(size_t)gk*ldx + gn];
            if(gk+1 < K) bv1 = *(const float4*)&X[(size_t)(gk+1)*ldx + gn];
        } else {
            if(gk < K){
                if(gn+0<N) bv0.x = X[(size_t)gk*ldx + gn+0];
                if(gn+1<N) bv0.y = X[(size_t)gk*ldx + gn+1];
                if(gn+2<N) bv0.z = X[(size_t)gk*ldx + gn+2];
                if(gn+3<N) bv0.w = X[(size_t)gk*ldx + gn+3];
            }
            if(gk+1 < K){
                if(gn+0<N) bv1.x = X[(size_t)(gk+1)*ldx + gn+0];
                if(gn+1<N) bv1.y = X[(size_t)(gk+1)*ldx + gn+1];
                if(gn+2<N) bv1.z = X[(size_t)(gk+1)*ldx + gn+2];
                if(gn+3<N) bv1.w = X[(size_t)(gk+1)*ldx + gn+3];
            }
        }
    };
    auto storeT = [&](int b){
        #pragma unroll
        for(int u=0;u<4;u++){
            int kw = akw0 + 2*u;
            float l0,l1;
            aH[b][kw][am] = pack_hi(a0[u], a1[u], l0, l1);
            aL[b][kw][am] = pack_bf(l0, l1);
        }
        uint4 hw, lw;
        float l0,l1;
        hw.x = pack_hi(bv0.x, bv1.x, l0, l1); lw.x = pack_bf(l0, l1);
        hw.y = pack_hi(bv0.y, bv1.y, l0, l1); lw.y = pack_bf(l0, l1);
        hw.z = pack_hi(bv0.z, bv1.z, l0, l1); lw.z = pack_bf(l0, l1);
        hw.w = pack_hi(bv0.w, bv1.w, l0, l1); lw.w = pack_bf(l0, l1);
        *(uint4*)&bH[b][bkw][bn4] = hw;
        *(uint4*)&bL[b][bkw][bn4] = lw;
    };
    auto comp = [&](int b){
        uint32_t ah[2][4], al[2][4];
        #pragma unroll
        for(int mt=0; mt<2; mt++){
            int r0 = wm + mt*16 + gid;
            ah[mt][0]=aH[b][tig  ][r0];  ah[mt][1]=aH[b][tig  ][r0+8];
            ah[mt][2]=aH[b][4+tig][r0];  ah[mt][3]=aH[b][4+tig][r0+8];
            al[mt][0]=aL[b][tig  ][r0];  al[mt][1]=aL[b][tig  ][r0+8];
            al[mt][2]=aL[b][4+tig][r0];  al[mt][3]=aL[b][4+tig][r0+8];
        }
        #pragma unroll
        for(int nt=0; nt<8; nt++){
            int cn = wn + nt*8 + gid;
            uint32_t bh2[2], bl2[2];
            bh2[0]=bH[b][tig][cn]; bh2[1]=bH[b][4+tig][cn];
            bl2[0]=bL[b][tig][cn]; bl2[1]=bL[b][4+tig][cn];
            #pragma unroll
            for(int mt=0; mt<2; mt++){
                mma_bf16(acc[mt][nt], ah[mt], bh2);
                mma_bf16(acc[mt][nt], ah[mt], bl2);
                mma_bf16(acc[mt][nt], al[mt], bh2);
            }
        }
    };

    int ntiles = (K+15)>>4;
    loadT(0); storeT(0);
    __syncthreads();
    int buf = 0;
    for(int t=1; t<ntiles; t++){
        loadT(t);
        comp(buf);
        storeT(buf^1);
        __syncthreads();
        buf ^= 1;
    }
    comp(buf);

    float ssum = 0.f, ssq = 0.f;
    #pragma unroll
    for(int mt=0; mt<2; mt++){
        int r0 = bm + wm + mt*16 + gid;
        int r1 = r0 + 8;
        float rb0 = 0.f, rb1 = 0.f;
        if(!BIASCOL && Bv){
            if(r0 < M) rb0 = Bv[r0];
            if(r1 < M) rb1 = Bv[r1];
        }
        #pragma unroll
        for(int nt=0; nt<8; nt++){
            int gn = bn + wn + nt*8 + tig*2;
            float cb0 = 0.f, cb1 = 0.f;
            if(BIASCOL && Bv){
                if(gn   < N) cb0 = Bv[gn];
                if(gn+1 < N) cb1 = Bv[gn+1];
            }
            float v0 = acc[mt][nt][0] + (BIASCOL ? cb0 : rb0);
            float v1 = acc[mt][nt][1] + (BIASCOL ? cb1 : rb0);
            float v2 = acc[mt][nt][2] + (BIASCOL ? cb0 : rb1);
            float v3 = acc[mt][nt][3] + (BIASCOL ? cb1 : rb1);
            if(ACT){ v0=gelu_f(v0); v1=gelu_f(v1); v2=gelu_f(v2); v3=gelu_f(v3); }
            if(DUAL){
                if(r0 < M){
                    float* d = (r0 < CH) ? &C[(size_t)r0*N] : &C2[(size_t)(r0-CH)*N];
                    float w0 = (r0 < CH) ? v0 : gelu_f(v0);
                    float w1 = (r0 < CH) ? v1 : gelu_f(v1);
                    if(gn   < N) d[gn]   = w0;
                    if(gn+1 < N) d[gn+1] = w1;
                }
                if(r1 < M){
                    float* d = (r1 < CH) ? &C[(size_t)r1*N] : &C2[(size_t)(r1-CH)*N];
                    float w2 = (r1 < CH) ? v2 : gelu_f(v2);
                    float w3 = (r1 < CH) ? v3 : gelu_f(v3);
                    if(gn   < N) d[gn]   = w2;
                    if(gn+1 < N) d[gn+1] = w3;
                }
            } else {
                if(r0 < M){
                    if(gn   < N){ C[(size_t)r0*N + gn]   = v0; if(STATS){ ssum+=v0; ssq=fmaf(v0,v0,ssq);} }
                    if(gn+1 < N){ C[(size_t)r0*N + gn+1] = v1; if(STATS){ ssum+=v1; ssq=fmaf(v1,v1,ssq);} }
                }
                if(r1 < M){
                    if(gn   < N){ C[(size_t)r1*N + gn]   = v2; if(STATS){ ssum+=v2; ssq=fmaf(v2,v2,ssq);} }
                    if(gn+1 < N){ C[(size_t)r1*N + gn+1] = v3; if(STATS){ ssum+=v3; ssq=fmaf(v3,v3,ssq);} }
                }
            }
        }
    }
    if(STATS){
        #pragma unroll
        for(int o=16;o>0;o>>=1){
            ssum += __shfl_down_sync(0xffffffffu, ssum, o);
            ssq  += __shfl_down_sync(0xffffffffu, ssq,  o);
        }
        __shared__ double ds[8], ds2[8];
        if(lane==0){ ds[wid]=(double)ssum; ds2[wid]=(double)ssq; }
        __syncthreads();
        if(tid==0){
            double a=0,b=0;
            #pragma unroll
            for(int k=0;k<8;k++){ a+=ds[k]; b+=ds2[k]; }
            atomicAdd(&g_stats[0], a);
            atomicAdd(&g_stats[1], b);
        }
    }
}

// ---------------- partial DFT chain (col-major h) ------------------------------
__global__ void dft_z_k(const float* __restrict__ h){
    __shared__ float sh[32*54];
    __shared__ float bc[324], bs[324];
    int t = threadIdx.x;                // 192
    long rowbase = (long)blockIdx.x*32;
    for(int i=t;i<324;i+=192){ bc[i]=d_c12[i]; bs[i]=d_s12[i]; }
    long gbase = rowbase*54;
    const long TOT = (long)CH*S2*54;
    for(int i=t;i<32*54;i+=192){
        long g = gbase + i;
        sh[i] = (g < TOT) ? h[g] : 0.f;
    }
    __syncthreads();
    int r = t/6, kz = t%6;
    long row = rowbase + r;
    if(row < (long)CH*S2){
        float re=0.f, im=0.f;
        const float* x = &sh[r*54];
        #pragma unroll
        for(int z=0;z<54;z++){
            float v = x[z];
            re = fmaf(v, bc[kz*54+z], re);
            im = fmaf(-v, bs[kz*54+z], im);
        }
        g_A1[row*6+kz] = make_float2(re, im);
    }
}

__global__ void dft_y_k(){
    __shared__ float2 sh[324];
    int t = threadIdx.x;                // 128
    int cx = blockIdx.x;
    const float2* src = g_A1 + (size_t)cx*324;
    for(int i=t;i<324;i+=128) sh[i] = src[i];
    __syncthreads();
    if(t < 72){
        int ky = t/6, kz = t%6;
        float re=0.f, im=0.f;
        for(int y=0;y<54;y++){
            float2 v = sh[y*6+kz];
            float c = d_c12[ky*54+y], s = d_s12[ky*54+y];
            re += v.x*c + v.y*s;
            im += v.y*c - v.x*s;
        }
        g_A2[(size_t)cx*72 + t] = make_float2(re, im);
    }
}

__global__ void dft_x_k(){
    __shared__ float2 sh[S*Q72];
    int t = threadIdx.x;                // 256
    int c = blockIdx.x;
    const float2* src = g_A2 + (size_t)c*(S*Q72);
    for(int i=t;i<S*Q72;i+=256) sh[i] = src[i];
    __syncthreads();
    for(int u=t; u<NMODE; u+=256){
        int kx = u/72, q = u%72;
        float re=0.f, im=0.f;
        for(int x=0;x<54;x++){
            float2 v = sh[x*72+q];
            float cc = d_c12[kx*54+x], s = d_s12[kx*54+x];
            re += v.x*cc + v.y*s;
            im += v.y*cc - v.x*s;
        }
        g_A3[(size_t)c*NMODE + u] = make_float2(re, im);
    }
}

__global__ void mix_k(const float2* __restrict__ wp){
    __shared__ float2 a[86];
    int m = blockIdx.x;                 // 864
    int t = threadIdx.x;                // 96
    int kx = m/72, ky = (m%72)/6, kz = m%6;
    if(t < 86) a[t] = g_A3[(size_t)t*NMODE + m];
    __syncthreads();
    if(t < 86){
        int cblk = (kx>=6)*2 + (ky>=6);
        int mloc = (kx%6)*36 + (ky%6)*6 + kz;
        const float2* w = wp + ((size_t)cblk*216 + mloc)*7396 + t;
        float re=0.f, im=0.f;
        for(int i=0;i<86;i++){
            float2 av = a[i];
            float2 wv = w[(size_t)i*86];
            re += av.x*wv.x - av.y*wv.y;
            im += av.x*wv.y + av.y*wv.x;
        }
        g_M3[(size_t)t*NMODE + m] = make_float2(re, im);
    }
}

__global__ void inv_x_k(){
    __shared__ float2 sh[NMODE];
    int t = threadIdx.x;                // 256
    int c = blockIdx.x;
    for(int i=t;i<NMODE;i+=256) sh[i] = g_M3[(size_t)c*NMODE + i];
    __syncthreads();
    for(int u=t; u<S*Q72; u+=256){
        int x = u/72, q = u%72;
        float re=0.f, im=0.f;
        #pragma unroll
        for(int p=0;p<12;p++){
            float2 v = sh[p*72+q];
            float cc = d_c12[p*54+x], s = d_s12[p*54+x];
            re += v.x*cc - v.y*s;
            im += v.x*s  + v.y*cc;
        }
        g_B2[(size_t)c*(S*Q72) + u] = make_float2(re, im);
    }
}

__global__ void inv_y_k(){
    __shared__ float2 sh[72];
    int t = threadIdx.x;                // 128
    int cx = blockIdx.x;
    if(t < 72) sh[t] = g_B2[(size_t)cx*72 + t];
    __syncthreads();
    for(int u=t; u<324; u+=128){
        int y = u/6, kz = u%6;
        float re=0.f, im=0.f;
        #pragma unroll
        for(int ky=0;ky<12;ky++){
            float2 v = sh[ky*6+kz];
            float cc = d_c12[ky*54+y], s = d_s12[ky*54+y];
            re += v.x*cc - v.y*s;
            im += v.x*s  + v.y*cc;
        }
        g_B1[(size_t)cx*324 + u] = make_float2(re, im);
    }
}

// inv-z with fused stats accumulation
__global__ void inv_z_k(){
    __shared__ float2 sh[324];
    int t = threadIdx.x;                // 256
    int cx = blockIdx.x;
    for(int i=t;i<324;i+=256) sh[i] = g_B1[(size_t)cx*324 + i];
    __syncthreads();
    const float inv = 1.0f/157464.0f;
    float ssum=0.f, ssq=0.f;
    for(int u=t; u<S2; u+=256){
        int y = u/54, z = u%54;
        const float2* b = &sh[y*6];
        float v = b[0].x;
        #pragma unroll
        for(int kz=1;kz<6;kz++){
            float cc = d_c12[kz*54+z], s = d_s12[kz*54+z];
            v += 2.f*(b[kz].x*cc - b[kz].y*s);
        }
        v *= inv;
        g_hf[(size_t)cx*S2 + u] = v;
        ssum += v; ssq = fmaf(v,v,ssq);
    }
    #pragma unroll
    for(int o=16;o>0;o>>=1){
        ssum += __shfl_down_sync(0xffffffffu, ssum, o);
        ssq  += __shfl_down_sync(0xffffffffu, ssq,  o);
    }
    __shared__ double ds[8], ds2[8];
    int w = t>>5;
    if((t&31)==0){ ds[w]=(double)ssum; ds2[w]=(double)ssq; }
    __syncthreads();
    if(t==0){
        double a=0,b=0;
        #pragma unroll
        for(int k=0;k<8;k++){ a+=ds[k]; b+=ds2[k]; }
        atomicAdd(&g_stats[0], a);
        atomicAdd(&g_stats[1], b);
    }
}

// ---------------- combine (fp64-free) ------------------------------------------
__global__ void combine_k(const float4* __restrict__ buf, const float4* __restrict__ add,
                          const float* __restrict__ gw, const float* __restrict__ gb,
                          float4* __restrict__ h, int actflag){
    long i = (long)blockIdx.x*blockDim.x + threadIdx.x;
    if(i >= (CS>>2)) return;
    float fmu = g_musw[0];
    float rs  = g_musw[1];
    int c = (int)((i<<2) / S3);
    float sw = rs*gw[c], sb = gb[c];
    float4 u = buf[i], a = add[i];
    float4 o;
    o.x = (u.x-fmu)*sw + sb + a.x;
    o.y = (u.y-fmu)*sw + sb + a.y;
    o.z = (u.z-fmu)*sw + sb + a.z;
    o.w = (u.w-fmu)*sw + sb + a.w;
    if(actflag){ o.x=gelu_f(o.x); o.y=gelu_f(o.y); o.z=gelu_f(o.z); o.w=gelu_f(o.w); }
    h[i] = o;
}

// ---------------- GNO head (row-major, compacted) ------------------------------
__global__ void embed_k(const float* __restrict__ pts, float* __restrict__ out, int n){
    int i = blockIdx.x*blockDim.x + threadIdx.x;
    if(i >= n) return;
    #pragma unroll
    for(int d=0; d<3; d++){
        float x = pts[i*3+d];
        #pragma unroll
        for(int f=0; f<8; f++){
            float fr = powf(1e-4f, (float)f/8.0f);
            float a = x*fr;
            out[(size_t)i*48 + d*16 + f]     = cosf(a);
            out[(size_t)i*48 + d*16 + 8 + f] = sinf(a);
        }
    }
}

__global__ void crop_k(){
    int n = blockIdx.x*256 + threadIdx.x;
    int c = blockIdx.y;
    if(n >= NOUT) return;
    int i = n/2304, j = (n/48)%48, k = n%48;
    g_fy[(size_t)n*CH + c] = g_h[((size_t)(c*S + i)*S + j)*S + k];
}

__global__ void k1_fuse_k(){
    long gt = (long)blockIdx.x*256 + threadIdx.x;
    int s  = (int)(gt >> 7);
    if(s >= g_mtot[0]) return;
    int c4 = ((int)gt & 127) << 2;
    int idx = g_cnb[s];
    int i = g_ci[s];
    float4 y = *(const float4*)&g_y1[(size_t)idx*512 + c4];
    float4 q = *(const float4*)&g_q1[(size_t)i*512 + c4];
    float4 o;
    o.x = gelu_f(y.x+q.x); o.y = gelu_f(y.y+q.y);
    o.z = gelu_f(y.z+q.z); o.w = gelu_f(y.w+q.w);
    *(float4*)&g_k1[(size_t)s*512 + c4] = o;
}

__global__ void gno_reduce_k(){
    int i = blockIdx.x;                 // NIN
    int c = threadIdx.x;                // 96 (86 active)
    __shared__ int sidx[KNB];
    __shared__ int sbase, scnt;
    if(c == 0){ sbase = g_base[i]; scnt = g_cnt[i]; }
    __syncthreads();
    if(c < scnt) sidx[c] = g_cnb[sbase + c];
    __syncthreads();
    if(c >= CH) return;
    float acc = 0.f;
    int cnt = scnt;
    for(int j=0; j<cnt; j++){
        acc += g_k3[((size_t)(sbase+j))*CH + c] * g_fy[(size_t)sidx[j]*CH + c];
    }
    float den = (float)(cnt > 1 ? cnt : 1);
    g_gv[(size_t)i*CH + c] = acc/den;
}

__global__ void p2_k(const float* __restrict__ w, const float* __restrict__ b,
                     float* __restrict__ out){
    int warp = threadIdx.x>>5, lane = threadIdx.x&31;
    int row = blockIdx.x*8 + warp;
    if(row >= NIN) return;
    const float* pr = g_p1 + (size_t)row*256;
    float acc = 0.f;
    #pragma unroll
    for(int f=lane; f<256; f+=32) acc = fmaf(w[f], pr[f], acc);
    #pragma unroll
    for(int o=16;o>0;o>>=1) acc += __shfl_down_sync(0xffffffffu, acc, o);
    if(lane==0) out[row] = acc + b[0];
}

// ---------------- host orchestration -----------------------------------------
static void bgemm(const float* W, int lda, const float* X, int ldx,
                  const float* B, float* C,
                  int M, int K, int N, int act, int biascol, int stats,
                  const int* Mdev = 0){
    dim3 grid((N+127)/128, (M+127)/128);
    if(biascol){
        if(act) bgemm_k<1,1,0,0><<<grid,256>>>(W,lda,X,ldx,B,C,0,M,K,N,Mdev);
        else    bgemm_k<1,0,0,0><<<grid,256>>>(W,lda,X,ldx,B,C,0,M,K,N,Mdev);
    } else if(stats){
        bgemm_k<0,0,1,0><<<grid,256>>>(W,lda,X,ldx,B,C,0,M,K,N,Mdev);
    } else {
        if(act) bgemm_k<0,1,0,0><<<grid,256>>>(W,lda,X,ldx,B,C,0,M,K,N,Mdev);
        else    bgemm_k<0,0,0,0><<<grid,256>>>(W,lda,X,ldx,B,C,0,M,K,N,Mdev);
    }
}

static void bgemm_dual(const float* W, const float* X, const float* B,
                       float* C1, float* C2){
    dim3 grid((S3+127)/128, (MDUAL+127)/128);
    bgemm_k<0,0,0,1><<<grid,256>>>(W, CH, X, S3, B, C1, C2, MDUAL, CH, S3, 0);
}

extern "C" void kernel_launch(void* const* d_in, const int* in_sizes, int n_in,
                              void* d_out, int out_size){
    const float* x_in   = (const float*)d_in[0];
    const float* x_out  = (const float*)d_in[1];
    const float* df     = (const float*)d_in[2];
    const int*   nb_idx = (const int*)  d_in[3];
    const void*  nb_mask= (const void*) d_in[4];
    const float* w_lift = (const float*)d_in[5];
    const float* b_lift = (const float*)d_in[6];
    const float* spec_wr= (const float*)d_in[7];
    const float* spec_wi= (const float*)d_in[8];
    const float* w_skip = (const float*)d_in[9];
    const float* b_skip = (const float*)d_in[10];
    const float* mlp1_w = (const float*)d_in[11];
    const float* mlp1_b = (const float*)d_in[12];
    const float* mlp2_w = (const float*)d_in[13];
    const float* mlp2_b = (const float*)d_in[14];
    const float* wms    = (const float*)d_in[15];
    const float* bms    = (const float*)d_in[16];
    const float* g1w    = (const float*)d_in[17];
    const float* g1b    = (const float*)d_in[18];
    const float* g2w    = (const float*)d_in[19];
    const float* g2b    = (const float*)d_in[20];
    const float* k1w    = (const float*)d_in[21];
    const float* k1b    = (const float*)d_in[22];
    const float* k2w    = (const float*)d_in[23];
    const float* k2b    = (const float*)d_in[24];
    const float* k3w    = (const float*)d_in[25];
    const float* k3b    = (const float*)d_in[26];
    const float* p1w    = (const float*)d_in[27];
    const float* p1b    = (const float*)d_in[28];
    const float* p2w    = (const float*)d_in[29];
    const float* p2b    = (const float*)d_in[30];
    float* out = (float*)d_out;

    float *ph, *pskip, *phf, *pt1, *pxoe, *pxie, *py1, *pq1, *pk1, *pk2, *pk3, *pgv, *pp1;
    float *ptwy, *ptwq, *ptw2, *ptw3, *ptwp, *pwd, *pbd;
    float2 *pwp;
    int *pmtot;
    cudaGetSymbolAddress((void**)&ph,    g_h);
    cudaGetSymbolAddress((void**)&pskip, g_skip);
    cudaGetSymbolAddress((void**)&phf,   g_hf);
    cudaGetSymbolAddress((void**)&pt1,   g_t1);
    cudaGetSymbolAddress((void**)&pxoe,  g_xoe);
    cudaGetSymbolAddress((void**)&pxie,  g_xie);
    cudaGetSymbolAddress((void**)&py1,   g_y1);
    cudaGetSymbolAddress((void**)&pq1,   g_q1);
    cudaGetSymbolAddress((void**)&pk1,   g_k1);
    cudaGetSymbolAddress((void**)&pk2,   g_k2);
    cudaGetSymbolAddress((void**)&pk3,   g_k3);
    cudaGetSymbolAddress((void**)&pgv,   g_gv);
    cudaGetSymbolAddress((void**)&pp1,   g_p1);
    cudaGetSymbolAddress((void**)&ptwy,  g_twy);
    cudaGetSymbolAddress((void**)&ptwq,  g_twq);
    cudaGetSymbolAddress((void**)&ptw2,  g_tw2);
    cudaGetSymbolAddress((void**)&ptw3,  g_tw3);
    cudaGetSymbolAddress((void**)&ptwp,  g_twp);
    cudaGetSymbolAddress((void**)&pwd,   g_wd);
    cudaGetSymbolAddress((void**)&pbd,   g_bd);
    cudaGetSymbolAddress((void**)&pwp,   g_wp);
    cudaGetSymbolAddress((void**)&pmtot, g_mtot);

    // prep
    basis_k<<<2,384>>>();
    detect_mask_k<<<1,256>>>((const unsigned char*)nb_mask);
    count_k<<<NIN/256,256>>>(nb_mask);
    scan_k<<<1,256>>>();
    fill_k<<<NIN/256,256>>>(nb_idx, nb_mask);
    zero_stats_k<<<1,1>>>();
    {
        dim3 g((S3+255)/256, CH);
        lift_k<<<g,256>>>(df, x_out, w_lift, b_lift);
    }
    bgemm(w_skip, CH, ph, S3, b_skip, pskip, CH, CH, S3, 0, 0, 0);
    repack_k<<<(int)((25560576L+255)/256),256>>>(spec_wr, spec_wi);
    stack_k<<<(4*MDUAL*CH+255)/256,256>>>(wms, mlp1_w, bms, mlp1_b);
    transpose_k<<<(512*48 +255)/256,256>>>(k1w, ptwy, 512,  48,  96, 0,  512);
    transpose_k<<<(512*48 +255)/256,256>>>(k1w, ptwq, 512,  48,  96, 48, 512);
    transpose_k<<<(256*512+255)/256,256>>>(k2w, ptw2, 256, 512, 512, 0,  256);
    transpose_k<<<(86*256 +255)/256,256>>>(k3w, ptw3,  86, 256, 256, 0,   88);
    transpose_k<<<(256*86 +255)/256,256>>>(p1w, ptwp, 256,  86,  86, 0,  256);

    // FNO layers
    for(int l=0;l<4;l++){
        int act = (l<3) ? 1 : 0;
        if(l > 0)
            bgemm(w_skip + (size_t)l*CH*CH, CH, ph, S3, b_skip + l*CH, pskip, CH, CH, S3, 0, 0, 0);
        dft_z_k<<<(CH*S2+31)/32, 192>>>(ph);
        dft_y_k<<<CH*S, 128>>>();
        dft_x_k<<<CH, 256>>>();
        mix_k<<<NMODE, 96>>>(pwp + (size_t)l*WLAYER);
        inv_x_k<<<CH, 256>>>();
        inv_y_k<<<CH*S, 128>>>();
        inv_z_k<<<CH*S, 256>>>();
        finalize_stats_k<<<1,1>>>();
        combine_k<<<((CS>>2)+255)/256,256>>>((const float4*)phf,(const float4*)pskip,
                                             g1w + l*CH, g1b + l*CH, (float4*)ph, act);
        // fused mskip + mlp1: rows 0..85 -> pskip (no act), rows 86..171 -> pt1 (gelu)
        bgemm_dual(pwd + (size_t)l*MDUAL*CH, ph, pbd + (size_t)l*MDUAL, pskip, pt1);
        bgemm(mlp2_w + (size_t)l*CH*CH, CH, pt1, S3, mlp2_b + l*CH, phf, CH, CH, S3, 0, 0, 1);
        finalize_stats_k<<<1,1>>>();
        combine_k<<<((CS>>2)+255)/256,256>>>((const float4*)phf,(const float4*)pskip,
                                             g2w + l*CH, g2b + l*CH, (float4*)ph, act);
    }

    // crop f_y
    {
        dim3 g((NOUT+255)/256, CH);
        crop_k<<<g,256>>>();
    }

    // row-major embeddings
    embed_k<<<(NOUT+127)/128,128>>>(x_out, pxoe, NOUT);
    embed_k<<<(NIN +127)/128,128>>>(x_in,  pxie, NIN);

    // GNO kernel MLP on compacted rows
    bgemm(pxoe, 48, ptwy, 512, 0,   py1, NOUT, 48, 512, 0, 1, 0);
    bgemm(pxie, 48, ptwq, 512, k1b, pq1, NIN,  48, 512, 0, 1, 0);
    k1_fuse_k<<<(int)(((long)RTOT*128)/256),256>>>();
    bgemm(pk1, 512, ptw2, 256, k2b, pk2, RTOT, 512, 256, 1, 1, 0, pmtot);
    bgemm(pk2, 256, ptw3,  88, k3b, pk3, RTOT, 256, CH,  0, 1, 0, pmtot);

    // masked neighbor reduce
    gno_reduce_k<<<NIN, 96>>>();

    // projection MLP
    bgemm(pgv, CH, ptwp, 256, p1b, pp1, NIN, CH, 256, 1, 1, 0);
    p2_k<<<NIN/8,256>>>(p2w, p2b, out);
}

// round 15
// speedup vs baseline: 1.4940x; 1.0285x over previous
#include <cuda_runtime.h>
#include <cuda_bf16.h>
#include <math.h>
#include <cstdint>

// ----------------------------------------------------------------------------
// FNO-GNO forward, sm_103. Round 15: round-14 + k1 gather/GELU fused into the
// k2 GEMM A-loader (row-contiguous, sector-efficient). g_k1 eliminated.
// ----------------------------------------------------------------------------

#define S 54
#define S2 2916
#define S3 157464
#define CH 86
#define CS 13541904        // 86 * S3
#define NOUT 110592        // 48^3
#define NIN 8192
#define KNB 24
#define RTOT 196608        // NIN*KNB
#define MO 6
#define Q72 72
#define NMODE 864
#define WLAYER 6390144     // 4*216*86*86 (float2 per layer)
#define EPSGN 1e-5
#define MDUAL 172          // 2*CH stacked rows

// ---------------- device scratch ---------------------------------------------
__device__ float  g_h   [CS];
__device__ float  g_skip[CS];
__device__ float  g_hf  [CS];
__device__ float  g_t1  [CS];
__device__ float2 g_A1[CH*S2*MO];
__device__ float2 g_A2[CH*S*Q72];
__device__ float2 g_A3[CH*NMODE];
__device__ float2 g_M3[CH*NMODE];
__device__ float2 g_B2[CH*S*Q72];
__device__ float2 g_B1[CH*S2*MO];
__device__ float2 g_wp[4*WLAYER];
__device__ float  g_xoe[(size_t)NOUT*48];
__device__ float  g_xie[(size_t)NIN*48];
__device__ float  g_fy [(size_t)NOUT*CH];
__device__ float  g_y1 [(size_t)NOUT*512];
__device__ float  g_q1 [(size_t)NIN*512];
__device__ float  g_k2 [(size_t)RTOT*256];
__device__ float  g_k3 [(size_t)RTOT*CH];
__device__ float  g_gv [(size_t)NIN*CH];
__device__ float  g_p1 [(size_t)NIN*256];
__device__ float  g_twy[48*512];
__device__ float  g_twq[48*512];
__device__ float  g_tw2[512*256];
__device__ float  g_tw3[256*88];
__device__ float  g_twp[86*256];
__device__ float  g_wd [4*MDUAL*CH];        // stacked [wms; mlp1_w] per layer
__device__ float  g_bd [4*MDUAL];           // stacked [bms; mlp1_b] per layer
__device__ int    g_cnt [NIN];
__device__ int    g_base[NIN];
__device__ int    g_ci  [RTOT];
__device__ int    g_cnb [RTOT];
__device__ int    g_mtot[4];
__device__ double g_stats[2];
__device__ float  g_musw[2];                // finalized (mu, rs)
__device__ float  d_c12[648], d_s12[648];
__device__ int    g_mask_fmt;

__device__ __forceinline__ float gelu_f(float x){
    return 0.5f*x*(1.0f+erff(x*0.7071067811865476f));
}

// ---------------- bf16 mma helpers --------------------------------------------
__device__ __forceinline__ uint32_t pack_hi(float x0, float x1,
                                            float& r0, float& r1){
    __nv_bfloat16 h0 = __float2bfloat16(x0);
    __nv_bfloat16 h1 = __float2bfloat16(x1);
    r0 = x0 - __bfloat162float(h0);
    r1 = x1 - __bfloat162float(h1);
    __nv_bfloat162 t = __halves2bfloat162(h0, h1);
    return *(uint32_t*)&t;
}
__device__ __forceinline__ uint32_t pack_bf(float x0, float x1){
    __nv_bfloat162 t = __floats2bfloat162_rn(x0, x1);
    return *(uint32_t*)&t;
}
__device__ __forceinline__ void mma_bf16(float* c, const uint32_t* a, const uint32_t* b){
    asm volatile(
        "mma.sync.aligned.m16n8k16.row.col.f32.bf16.bf16.f32 "
        "{%0,%1,%2,%3}, {%4,%5,%6,%7}, {%8,%9}, {%0,%1,%2,%3};"
        : "+f"(c[0]),"+f"(c[1]),"+f"(c[2]),"+f"(c[3])
        : "r"(a[0]),"r"(a[1]),"r"(a[2]),"r"(a[3]), "r"(b[0]),"r"(b[1]));
}

// ---------------- mask dtype detection ---------------------------------------
__global__ void detect_mask_k(const unsigned char* __restrict__ m){
    __shared__ int s_f1, s_f3, s_nzna, s_oddw;
    if(threadIdx.x==0){ s_f1=0; s_f3=0; s_nzna=0; s_oddw=0; }
    __syncthreads();
    for(int i=threadIdx.x; i<4096; i+=blockDim.x){
        unsigned char b = m[i];
        int off = i & 3;
        if(b){
            if(off==1 && b==0x3F) atomicOr(&s_f1, 1);
            if(off==3 && b==0x3F) atomicOr(&s_f3, 1);
            if(off!=0)            atomicOr(&s_nzna, 1);
        }
    }
    const unsigned int* w = (const unsigned int*)m;
    for(int i=threadIdx.x; i<1024; i+=blockDim.x){
        if((i & 1) && w[i]) atomicOr(&s_oddw, 1);
    }
    __syncthreads();
    if(threadIdx.x==0){
        int fmt;
        if(s_f1)        fmt = 3;
        else if(s_f3)   fmt = 2;
        else if(s_nzna) fmt = 0;
        else if(s_oddw) fmt = 1;
        else            fmt = 4;
        g_mask_fmt = fmt;
    }
}
__device__ __forceinline__ int mask_at(const void* p, long r, int fmt){
    switch(fmt){
        case 0: return ((const unsigned char*)p)[r] != 0;
        case 1: return ((const int*)p)[r] != 0;
        case 2: return ((const float*)p)[r] != 0.f;
        case 3: return ((const unsigned short*)p)[r] != 0;
        default:return ((const long long*)p)[r] != 0;
    }
}

// ---------------- compaction ---------------------------------------------------
__global__ void count_k(const void* __restrict__ nb_mask){
    int i = blockIdx.x*256 + threadIdx.x;
    if(i >= NIN) return;
    int fmt = g_mask_fmt;
    int c = 0;
    for(int j=0;j<KNB;j++) c += mask_at(nb_mask, (long)i*KNB + j, fmt);
    g_cnt[i] = c;
}

__global__ void scan_k(){
    __shared__ int part[256];
    int t = threadIdx.x;
    int local[32];
    int s = 0;
    #pragma unroll
    for(int u=0;u<32;u++){
        local[u] = s;
        s += g_cnt[t*32 + u];
    }
    part[t] = s;
    __syncthreads();
    if(t == 0){
        int run = 0;
        for(int k=0;k<256;k++){ int v = part[k]; part[k] = run; run += v; }
        g_mtot[0] = run;
    }
    __syncthreads();
    int off = part[t];
    #pragma unroll
    for(int u=0;u<32;u++) g_base[t*32 + u] = off + local[u];
}

__global__ void fill_k(const int* __restrict__ nb_idx, const void* __restrict__ nb_mask){
    int i = blockIdx.x*256 + threadIdx.x;
    if(i >= NIN) return;
    int fmt = g_mask_fmt;
    int base = g_base[i], p = 0;
    for(int j=0;j<KNB;j++){
        if(mask_at(nb_mask, (long)i*KNB + j, fmt)){
            g_ci [base+p] = i;
            g_cnb[base+p] = nb_idx[i*KNB + j];
            p++;
        }
    }
}

// ---------------- prep -------------------------------------------------------
__global__ void basis_k(){
    int t = blockIdx.x*blockDim.x + threadIdx.x;
    if(t >= 648) return;
    int p = t/54, z = t%54;
    int ef = (p<6) ? p : (p+42);
    int m = (ef*z) % 54;
    double th = 6.283185307179586476925286766559 * (double)m / 54.0;
    d_c12[t] = (float)cos(th);
    d_s12[t] = (float)sin(th);
}
__global__ void zero_stats_k(){ g_stats[0]=0.0; g_stats[1]=0.0; }

__global__ void finalize_stats_k(){
    double mu  = g_stats[0]/(double)CS;
    double var = g_stats[1]/(double)CS - mu*mu;
    g_musw[0] = (float)mu;
    g_musw[1] = (float)rsqrt(var + EPSGN);
    g_stats[0] = 0.0;
    g_stats[1] = 0.0;
}

__global__ void repack_k(const float* __restrict__ wr, const float* __restrict__ wi){
    long idx = (long)blockIdx.x*256 + threadIdx.x;
    if(idx >= 25560576L) return;
    long x = idx;
    int o = (int)(x%86); x/=86;
    int i = (int)(x%86); x/=86;
    int mloc = (int)(x%216); x/=216;
    long lb = x;
    long src = ((lb*86 + i)*86 + o)*216 + mloc;
    g_wp[idx] = make_float2(wr[src], wi[src]);
}

__global__ void transpose_k(const float* __restrict__ src, float* __restrict__ dst,
                            int O, int Kt, int Ktot, int k0, int ldd){
    int t = blockIdx.x*256 + threadIdx.x;
    if(t >= O*Kt) return;
    int k = t / O, o = t % O;
    dst[(size_t)k*ldd + o] = src[(size_t)o*Ktot + k0 + k];
}

__global__ void stack_k(const float* __restrict__ wms, const float* __restrict__ mlp1w,
                        const float* __restrict__ bms, const float* __restrict__ mlp1b){
    int t = blockIdx.x*256 + threadIdx.x;
    int per = MDUAL*CH;
    if(t < 4*per){
        int l = t / per, r = (t % per) / CH, c = t % CH;
        float v = (r < CH) ? wms[((size_t)l*CH + r)*CH + c]
                           : mlp1w[((size_t)l*CH + (r-CH))*CH + c];
        g_wd[t] = v;
    }
    if(t < 4*MDUAL){
        int l = t / MDUAL, r = t % MDUAL;
        g_bd[t] = (r < CH) ? bms[l*CH + r] : mlp1b[l*CH + (r-CH)];
    }
}

// ---------------- lift --------------------------------------------------------
__global__ void lift_k(const float* __restrict__ df, const float* __restrict__ xout,
                       const float* __restrict__ w, const float* __restrict__ b){
    int n = blockIdx.x*256 + threadIdx.x;
    int c = blockIdx.y;
    if(n >= S3) return;
    int i = n/S2, j = (n/S)%S, k = n%S;
    float v = 0.f;
    if(i < 48 && j < 48 && k < 48){
        int n48 = (i*48 + j)*48 + k;
        float f0 = df[n48], f1 = df[NOUT + n48];
        float f2 = xout[n48*3+0], f3 = xout[n48*3+1], f4 = xout[n48*3+2];
        const float* wr = &w[c*5];
        v = b[c] + wr[0]*f0 + wr[1]*f1 + wr[2]*f2 + wr[3]*f3 + wr[4]*f4;
    }
    g_h[(size_t)c*S3 + n] = v;
}

// ---------------- bf16x3 tensor GEMM (round-10 engine + GATHER A) --------------
// DUAL=1: rows < CH -> C (no act), rows >= CH -> C2 at (r-CH) with GELU.
// GATHER=1: A row r = gelu( y1[cnb[bm+r]][k] + q1[ci[bm+r]][k] ), K=512.
template<int BIASCOL, int ACT, int STATS, int DUAL, int GATHER>
__global__ __launch_bounds__(256, 2) void bgemm_k(
    const float* __restrict__ W, int lda,
    const float* __restrict__ X, int ldx,
    const float* __restrict__ Bv, float* __restrict__ C,
    float* __restrict__ C2,
    int M, int K, int N, const int* __restrict__ Mdev)
{
    if(Mdev) M = *Mdev;
    const int bm = blockIdx.y*128, bn = blockIdx.x*128;
    if(bm >= M) return;
    __shared__ uint32_t aH[2][8][136], aL[2][8][136];
    __shared__ uint32_t bH[2][8][136], bL[2][8][136];
    __shared__ int s_idx[GATHER ? 128 : 1], s_qi[GATHER ? 128 : 1];
    const int tid = threadIdx.x;
    const int wid = tid>>5, lane = tid&31;
    const int gid = lane>>2, tig = lane&3;
    const int wm = (wid>>1)*32;
    const int wn = (wid&1)*64;

    if(GATHER){
        if(tid < 128){
            int g = bm + tid;
            if(g < M){ s_idx[tid] = g_cnb[g]; s_qi[tid] = g_ci[g]; }
            else     { s_idx[tid] = 0;        s_qi[tid] = 0; }
        }
        __syncthreads();
    }

    float acc[2][8][4];
    #pragma unroll
    for(int a=0;a<2;a++)
        #pragma unroll
        for(int b=0;b<8;b++)
            #pragma unroll
            for(int c=0;c<4;c++) acc[a][b][c]=0.f;

    const int am   = tid & 127;
    const int akw0 = tid >> 7;         // also "half" for GATHER
    const int bkw  = tid >> 5;
    const int bn4  = lane * 4;

    float  a0[4], a1[4];               // non-gather A regs
    float  av[8];                      // gather A regs (8 consecutive k)
    float4 bv0, bv1;

    auto loadT = [&](int kt){
        int k0 = kt*16;
        int gm = bm + am;
        if(GATHER){
            int cb = k0 + akw0*8;
            if(gm < M){
                const float* yp = g_y1 + (size_t)s_idx[am]*512 + cb;
                const float* qp = g_q1 + (size_t)s_qi[am]*512 + cb;
                float4 ya = *(const float4*)yp;
                float4 yb = *(const float4*)(yp+4);
                float4 qa = *(const float4*)qp;
                float4 qb = *(const float4*)(qp+4);
                av[0]=gelu_f(ya.x+qa.x); av[1]=gelu_f(ya.y+qa.y);
                av[2]=gelu_f(ya.z+qa.z); av[3]=gelu_f(ya.w+qa.w);
                av[4]=gelu_f(yb.x+qb.x); av[5]=gelu_f(yb.y+qb.y);
                av[6]=gelu_f(yb.z+qb.z); av[7]=gelu_f(yb.w+qb.w);
            } else {
                #pragma unroll
                for(int u=0;u<8;u++) av[u]=0.f;
            }
        } else {
            #pragma unroll
            for(int u=0;u<4;u++){
                int gk = k0 + (akw0 + 2*u)*2;
                if(gm < M && gk+1 < K){
                    float2 v = *(const float2*)&W[(size_t)gm*lda + gk];
                    a0[u] = v.x; a1[u] = v.y;
                } else { a0[u]=0.f; a1[u]=0.f; }
            }
        }
        int gk = k0 + bkw*2;
        int gn = bn + bn4;
        bv0 = make_float4(0.f,0.f,0.f,0.f);
        bv1 = make_float4(0.f,0.f,0.f,0.f);
        if(gn + 3 < N){
            if(gk   < K) bv0 = *(const float4*)&X[(size_t)gk*ldx + gn];
            if(gk+1 < K) bv1 = *(const float4*)&X[(size_t)(gk+1)*ldx + gn];
        } else {
            if(gk < K){
                if(gn+0<N) bv0.x = X[(size_t)gk*ldx + gn+0];
                if(gn+1<N) bv0.y = X[(size_t)gk*ldx + gn+1];
                if(gn+2<N) bv0.z = X[(size_t)gk*ldx + gn+2];
                if(gn+3<N) bv0.w = X[(size_t)gk*ldx + gn+3];
            }
            if(gk+1 < K){
                if(gn+0<N) bv1.x = X[(size_t)(gk+1)*ldx + gn+0];
                if(gn+1<N) bv1.y = X[(size_t)(gk+1)*ldx + gn+1];
                if(gn+2<N) bv1.z = X[(size_t)(gk+1)*ldx + gn+2];
                if(gn+3<N) bv1.w = X[(size_t)(gk+1)*ldx + gn+3];
            }
        }
    };
    auto storeT = [&](int b){
        if(GATHER){
            #pragma unroll
            for(int u=0;u<4;u++){
                int kw = akw0*4 + u;
                float l0,l1;
                aH[b][kw][am] = pack_hi(av[2*u], av[2*u+1], l0, l1);
                aL[b][kw][am] = pack_bf(l0, l1);
            }
        } else {
            #pragma unroll
            for(int u=0;u<4;u++){
                int kw = akw0 + 2*u;
                float l0,l1;
                aH[b][kw][am] = pack_hi(a0[u], a1[u], l0, l1);
                aL[b][kw][am] = pack_bf(l0, l1);
            }
        }
        uint4 hw, lw;
        float l0,l1;
        hw.x = pack_hi(bv0.x, bv1.x, l0, l1); lw.x = pack_bf(l0, l1);
        hw.y = pack_hi(bv0.y, bv1.y, l0, l1); lw.y = pack_bf(l0, l1);
        hw.z = pack_hi(bv0.z, bv1.z, l0, l1); lw.z = pack_bf(l0, l1);
        hw.w = pack_hi(bv0.w, bv1.w, l0, l1); lw.w = pack_bf(l0, l1);
        *(uint4*)&bH[b][bkw][bn4] = hw;
        *(uint4*)&bL[b][bkw][bn4] = lw;
    };
    auto comp = [&](int b){
        uint32_t ah[2][4], al[2][4];
        #pragma unroll
        for(int mt=0; mt<2; mt++){
            int r0 = wm + mt*16 + gid;
            ah[mt][0]=aH[b][tig  ][r0];  ah[mt][1]=aH[b][tig  ][r0+8];
            ah[mt][2]=aH[b][4+tig][r0];  ah[mt][3]=aH[b][4+tig][r0+8];
            al[mt][0]=aL[b][tig  ][r0];  al[mt][1]=aL[b][tig  ][r0+8];
            al[mt][2]=aL[b][4+tig][r0];  al[mt][3]=aL[b][4+tig][r0+8];
        }
        #pragma unroll
        for(int nt=0; nt<8; nt++){
            int cn = wn + nt*8 + gid;
            uint32_t bh2[2], bl2[2];
            bh2[0]=bH[b][tig][cn]; bh2[1]=bH[b][4+tig][cn];
            bl2[0]=bL[b][tig][cn]; bl2[1]=bL[b][4+tig][cn];
            #pragma unroll
            for(int mt=0; mt<2; mt++){
                mma_bf16(acc[mt][nt], ah[mt], bh2);
                mma_bf16(acc[mt][nt], ah[mt], bl2);
                mma_bf16(acc[mt][nt], al[mt], bh2);
            }
        }
    };

    int ntiles = (K+15)>>4;
    loadT(0); storeT(0);
    __syncthreads();
    int buf = 0;
    for(int t=1; t<ntiles; t++){
        loadT(t);
        comp(buf);
        storeT(buf^1);
        __syncthreads();
        buf ^= 1;
    }
    comp(buf);

    float ssum = 0.f, ssq = 0.f;
    #pragma unroll
    for(int mt=0; mt<2; mt++){
        int r0 = bm + wm + mt*16 + gid;
        int r1 = r0 + 8;
        float rb0 = 0.f, rb1 = 0.f;
        if(!BIASCOL && Bv){
            if(r0 < M) rb0 = Bv[r0];
            if(r1 < M) rb1 = Bv[r1];
        }
        #pragma unroll
        for(int nt=0; nt<8; nt++){
            int gn = bn + wn + nt*8 + tig*2;
            float cb0 = 0.f, cb1 = 0.f;
            if(BIASCOL && Bv){
                if(gn   < N) cb0 = Bv[gn];
                if(gn+1 < N) cb1 = Bv[gn+1];
            }
            float v0 = acc[mt][nt][0] + (BIASCOL ? cb0 : rb0);
            float v1 = acc[mt][nt][1] + (BIASCOL ? cb1 : rb0);
            float v2 = acc[mt][nt][2] + (BIASCOL ? cb0 : rb1);
            float v3 = acc[mt][nt][3] + (BIASCOL ? cb1 : rb1);
            if(ACT){ v0=gelu_f(v0); v1=gelu_f(v1); v2=gelu_f(v2); v3=gelu_f(v3); }
            if(DUAL){
                if(r0 < M){
                    float* d = (r0 < CH) ? &C[(size_t)r0*N] : &C2[(size_t)(r0-CH)*N];
                    float w0 = (r0 < CH) ? v0 : gelu_f(v0);
                    float w1 = (r0 < CH) ? v1 : gelu_f(v1);
                    if(gn   < N) d[gn]   = w0;
                    if(gn+1 < N) d[gn+1] = w1;
                }
                if(r1 < M){
                    float* d = (r1 < CH) ? &C[(size_t)r1*N] : &C2[(size_t)(r1-CH)*N];
                    float w2 = (r1 < CH) ? v2 : gelu_f(v2);
                    float w3 = (r1 < CH) ? v3 : gelu_f(v3);
                    if(gn   < N) d[gn]   = w2;
                    if(gn+1 < N) d[gn+1] = w3;
                }
            } else {
                if(r0 < M){
                    if(gn   < N){ C[(size_t)r0*N + gn]   = v0; if(STATS){ ssum+=v0; ssq=fmaf(v0,v0,ssq);} }
                    if(gn+1 < N){ C[(size_t)r0*N + gn+1] = v1; if(STATS){ ssum+=v1; ssq=fmaf(v1,v1,ssq);} }
                }
                if(r1 < M){
                    if(gn   < N){ C[(size_t)r1*N + gn]   = v2; if(STATS){ ssum+=v2; ssq=fmaf(v2,v2,ssq);} }
                    if(gn+1 < N){ C[(size_t)r1*N + gn+1] = v3; if(STATS){ ssum+=v3; ssq=fmaf(v3,v3,ssq);} }
                }
            }
        }
    }
    if(STATS){
        #pragma unroll
        for(int o=16;o>0;o>>=1){
            ssum += __shfl_down_sync(0xffffffffu, ssum, o);
            ssq  += __shfl_down_sync(0xffffffffu, ssq,  o);
        }
        __shared__ double ds[8], ds2[8];
        if(lane==0){ ds[wid]=(double)ssum; ds2[wid]=(double)ssq; }
        __syncthreads();
        if(tid==0){
            double a=0,b=0;
            #pragma unroll
            for(int k=0;k<8;k++){ a+=ds[k]; b+=ds2[k]; }
            atomicAdd(&g_stats[0], a);
            atomicAdd(&g_stats[1], b);
        }
    }
}

// ---------------- partial DFT chain (col-major h) ------------------------------
__global__ void dft_z_k(const float* __restrict__ h){
    __shared__ float sh[32*54];
    __shared__ float bc[324], bs[324];
    int t = threadIdx.x;                // 192
    long rowbase = (long)blockIdx.x*32;
    for(int i=t;i<324;i+=192){ bc[i]=d_c12[i]; bs[i]=d_s12[i]; }
    long gbase = rowbase*54;
    const long TOT = (long)CH*S2*54;
    for(int i=t;i<32*54;i+=192){
        long g = gbase + i;
        sh[i] = (g < TOT) ? h[g] : 0.f;
    }
    __syncthreads();
    int r = t/6, kz = t%6;
    long row = rowbase + r;
    if(row < (long)CH*S2){
        float re=0.f, im=0.f;
        const float* x = &sh[r*54];
        #pragma unroll
        for(int z=0;z<54;z++){
            float v = x[z];
            re = fmaf(v, bc[kz*54+z], re);
            im = fmaf(-v, bs[kz*54+z], im);
        }
        g_A1[row*6+kz] = make_float2(re, im);
    }
}

__global__ void dft_y_k(){
    __shared__ float2 sh[324];
    int t = threadIdx.x;                // 128
    int cx = blockIdx.x;
    const float2* src = g_A1 + (size_t)cx*324;
    for(int i=t;i<324;i+=128) sh[i] = src[i];
    __syncthreads();
    if(t < 72){
        int ky = t/6, kz = t%6;
        float re=0.f, im=0.f;
        for(int y=0;y<54;y++){
            float2 v = sh[y*6+kz];
            float c = d_c12[ky*54+y], s = d_s12[ky*54+y];
            re += v.x*c + v.y*s;
            im += v.y*c - v.x*s;
        }
        g_A2[(size_t)cx*72 + t] = make_float2(re, im);
    }
}

__global__ void dft_x_k(){
    __shared__ float2 sh[S*Q72];
    int t = threadIdx.x;                // 256
    int c = blockIdx.x;
    const float2* src = g_A2 + (size_t)c*(S*Q72);
    for(int i=t;i<S*Q72;i+=256) sh[i] = src[i];
    __syncthreads();
    for(int u=t; u<NMODE; u+=256){
        int kx = u/72, q = u%72;
        float re=0.f, im=0.f;
        for(int x=0;x<54;x++){
            float2 v = sh[x*72+q];
            float cc = d_c12[kx*54+x], s = d_s12[kx*54+x];
            re += v.x*cc + v.y*s;
            im += v.y*cc - v.x*s;
        }
        g_A3[(size_t)c*NMODE + u] = make_float2(re, im);
    }
}

__global__ void mix_k(const float2* __restrict__ wp){
    __shared__ float2 a[86];
    int m = blockIdx.x;                 // 864
    int t = threadIdx.x;                // 96
    int kx = m/72, ky = (m%72)/6, kz = m%6;
    if(t < 86) a[t] = g_A3[(size_t)t*NMODE + m];
    __syncthreads();
    if(t < 86){
        int cblk = (kx>=6)*2 + (ky>=6);
        int mloc = (kx%6)*36 + (ky%6)*6 + kz;
        const float2* w = wp + ((size_t)cblk*216 + mloc)*7396 + t;
        float re=0.f, im=0.f;
        for(int i=0;i<86;i++){
            float2 av = a[i];
            float2 wv = w[(size_t)i*86];
            re += av.x*wv.x - av.y*wv.y;
            im += av.x*wv.y + av.y*wv.x;
        }
        g_M3[(size_t)t*NMODE + m] = make_float2(re, im);
    }
}

__global__ void inv_x_k(){
    __shared__ float2 sh[NMODE];
    int t = threadIdx.x;                // 256
    int c = blockIdx.x;
    for(int i=t;i<NMODE;i+=256) sh[i] = g_M3[(size_t)c*NMODE + i];
    __syncthreads();
    for(int u=t; u<S*Q72; u+=256){
        int x = u/72, q = u%72;
        float re=0.f, im=0.f;
        #pragma unroll
        for(int p=0;p<12;p++){
            float2 v = sh[p*72+q];
            float cc = d_c12[p*54+x], s = d_s12[p*54+x];
            re += v.x*cc - v.y*s;
            im += v.x*s  + v.y*cc;
        }
        g_B2[(size_t)c*(S*Q72) + u] = make_float2(re, im);
    }
}

__global__ void inv_y_k(){
    __shared__ float2 sh[72];
    int t = threadIdx.x;                // 128
    int cx = blockIdx.x;
    if(t < 72) sh[t] = g_B2[(size_t)cx*72 + t];
    __syncthreads();
    for(int u=t; u<324; u+=128){
        int y = u/6, kz = u%6;
        float re=0.f, im=0.f;
        #pragma unroll
        for(int ky=0;ky<12;ky++){
            float2 v = sh[ky*6+kz];
            float cc = d_c12[ky*54+y], s = d_s12[ky*54+y];
            re += v.x*cc - v.y*s;
            im += v.x*s  + v.y*cc;
        }
        g_B1[(size_t)cx*324 + u] = make_float2(re, im);
    }
}

// inv-z with fused stats accumulation
__global__ void inv_z_k(){
    __shared__ float2 sh[324];
    int t = threadIdx.x;                // 256
    int cx = blockIdx.x;
    for(int i=t;i<324;i+=256) sh[i] = g_B1[(size_t)cx*324 + i];
    __syncthreads();
    const float inv = 1.0f/157464.0f;
    float ssum=0.f, ssq=0.f;
    for(int u=t; u<S2; u+=256){
        int y = u/54, z = u%54;
        const float2* b = &sh[y*6];
        float v = b[0].x;
        #pragma unroll
        for(int kz=1;kz<6;kz++){
            float cc = d_c12[kz*54+z], s = d_s12[kz*54+z];
            v += 2.f*(b[kz].x*cc - b[kz].y*s);
        }
        v *= inv;
        g_hf[(size_t)cx*S2 + u] = v;
        ssum += v; ssq = fmaf(v,v,ssq);
    }
    #pragma unroll
    for(int o=16;o>0;o>>=1){
        ssum += __shfl_down_sync(0xffffffffu, ssum, o);
        ssq  += __shfl_down_sync(0xffffffffu, ssq,  o);
    }
    __shared__ double ds[8], ds2[8];
    int w = t>>5;
    if((t&31)==0){ ds[w]=(double)ssum; ds2[w]=(double)ssq; }
    __syncthreads();
    if(t==0){
        double a=0,b=0;
        #pragma unroll
        for(int k=0;k<8;k++){ a+=ds[k]; b+=ds2[k]; }
        atomicAdd(&g_stats[0], a);
        atomicAdd(&g_stats[1], b);
    }
}

// ---------------- combine (fp64-free) ------------------------------------------
__global__ void combine_k(const float4* __restrict__ buf, const float4* __restrict__ add,
                          const float* __restrict__ gw, const float* __restrict__ gb,
                          float4* __restrict__ h, int actflag){
    long i = (long)blockIdx.x*blockDim.x + threadIdx.x;
    if(i >= (CS>>2)) return;
    float fmu = g_musw[0];
    float rs  = g_musw[1];
    int c = (int)((i<<2) / S3);
    float sw = rs*gw[c], sb = gb[c];
    float4 u = buf[i], a = add[i];
    float4 o;
    o.x = (u.x-fmu)*sw + sb + a.x;
    o.y = (u.y-fmu)*sw + sb + a.y;
    o.z = (u.z-fmu)*sw + sb + a.z;
    o.w = (u.w-fmu)*sw + sb + a.w;
    if(actflag){ o.x=gelu_f(o.x); o.y=gelu_f(o.y); o.z=gelu_f(o.z); o.w=gelu_f(o.w); }
    h[i] = o;
}

// ---------------- GNO head (row-major, compacted) ------------------------------
__global__ void embed_k(const float* __restrict__ pts, float* __restrict__ out, int n){
    int i = blockIdx.x*blockDim.x + threadIdx.x;
    if(i >= n) return;
    #pragma unroll
    for(int d=0; d<3; d++){
        float x = pts[i*3+d];
        #pragma unroll
        for(int f=0; f<8; f++){
            float fr = powf(1e-4f, (float)f/8.0f);
            float a = x*fr;
            out[(size_t)i*48 + d*16 + f]     = cosf(a);
            out[(size_t)i*48 + d*16 + 8 + f] = sinf(a);
        }
    }
}

__global__ void crop_k(){
    int n = blockIdx.x*256 + threadIdx.x;
    int c = blockIdx.y;
    if(n >= NOUT) return;
    int i = n/2304, j = (n/48)%48, k = n%48;
    g_fy[(size_t)n*CH + c] = g_h[((size_t)(c*S + i)*S + j)*S + k];
}

__global__ void gno_reduce_k(){
    int i = blockIdx.x;                 // NIN
    int c = threadIdx.x;                // 96 (86 active)
    __shared__ int sidx[KNB];
    __shared__ int sbase, scnt;
    if(c == 0){ sbase = g_base[i]; scnt = g_cnt[i]; }
    __syncthreads();
    if(c < scnt) sidx[c] = g_cnb[sbase + c];
    __syncthreads();
    if(c >= CH) return;
    float acc = 0.f;
    int cnt = scnt;
    for(int j=0; j<cnt; j++){
        acc += g_k3[((size_t)(sbase+j))*CH + c] * g_fy[(size_t)sidx[j]*CH + c];
    }
    float den = (float)(cnt > 1 ? cnt : 1);
    g_gv[(size_t)i*CH + c] = acc/den;
}

__global__ void p2_k(const float* __restrict__ w, const float* __restrict__ b,
                     float* __restrict__ out){
    int warp = threadIdx.x>>5, lane = threadIdx.x&31;
    int row = blockIdx.x*8 + warp;
    if(row >= NIN) return;
    const float* pr = g_p1 + (size_t)row*256;
    float acc = 0.f;
    #pragma unroll
    for(int f=lane; f<256; f+=32) acc = fmaf(w[f], pr[f], acc);
    #pragma unroll
    for(int o=16;o>0;o>>=1) acc += __shfl_down_sync(0xffffffffu, acc, o);
    if(lane==0) out[row] = acc + b[0];
}

// ---------------- host orchestration -----------------------------------------
static void bgemm(const float* W, int lda, const float* X, int ldx,
                  const float* B, float* C,
                  int M, int K, int N, int act, int biascol, int stats,
                  const int* Mdev = 0){
    dim3 grid((N+127)/128, (M+127)/128);
    if(biascol){
        if(act) bgemm_k<1,1,0,0,0><<<grid,256>>>(W,lda,X,ldx,B,C,0,M,K,N,Mdev);
        else    bgemm_k<1,0,0,0,0><<<grid,256>>>(W,lda,X,ldx,B,C,0,M,K,N,Mdev);
    } else if(stats){
        bgemm_k<0,0,1,0,0><<<grid,256>>>(W,lda,X,ldx,B,C,0,M,K,N,Mdev);
    } else {
        if(act) bgemm_k<0,1,0,0,0><<<grid,256>>>(W,lda,X,ldx,B,C,0,M,K,N,Mdev);
        else    bgemm_k<0,0,0,0,0><<<grid,256>>>(W,lda,X,ldx,B,C,0,M,K,N,Mdev);
    }
}

static void bgemm_dual(const float* W, const float* X, const float* B,
                       float* C1, float* C2){
    dim3 grid((S3+127)/128, (MDUAL+127)/128);
    bgemm_k<0,0,0,1,0><<<grid,256>>>(W, CH, X, S3, B, C1, C2, MDUAL, CH, S3, 0);
}

extern "C" void kernel_launch(void* const* d_in, const int* in_sizes, int n_in,
                              void* d_out, int out_size){
    const float* x_in   = (const float*)d_in[0];
    const float* x_out  = (const float*)d_in[1];
    const float* df     = (const float*)d_in[2];
    const int*   nb_idx = (const int*)  d_in[3];
    const void*  nb_mask= (const void*) d_in[4];
    const float* w_lift = (const float*)d_in[5];
    const float* b_lift = (const float*)d_in[6];
    const float* spec_wr= (const float*)d_in[7];
    const float* spec_wi= (const float*)d_in[8];
    const float* w_skip = (const float*)d_in[9];
    const float* b_skip = (const float*)d_in[10];
    const float* mlp1_w = (const float*)d_in[11];
    const float* mlp1_b = (const float*)d_in[12];
    const float* mlp2_w = (const float*)d_in[13];
    const float* mlp2_b = (const float*)d_in[14];
    const float* wms    = (const float*)d_in[15];
    const float* bms    = (const float*)d_in[16];
    const float* g1w    = (const float*)d_in[17];
    const float* g1b    = (const float*)d_in[18];
    const float* g2w    = (const float*)d_in[19];
    const float* g2b    = (const float*)d_in[20];
    const float* k1w    = (const float*)d_in[21];
    const float* k1b    = (const float*)d_in[22];
    const float* k2w    = (const float*)d_in[23];
    const float* k2b    = (const float*)d_in[24];
    const float* k3w    = (const float*)d_in[25];
    const float* k3b    = (const float*)d_in[26];
    const float* p1w    = (const float*)d_in[27];
    const float* p1b    = (const float*)d_in[28];
    const float* p2w    = (const float*)d_in[29];
    const float* p2b    = (const float*)d_in[30];
    float* out = (float*)d_out;

    float *ph, *pskip, *phf, *pt1, *pxoe, *pxie, *py1, *pq1, *pk2, *pk3, *pgv, *pp1;
    float *ptwy, *ptwq, *ptw2, *ptw3, *ptwp, *pwd, *pbd;
    float2 *pwp;
    int *pmtot;
    cudaGetSymbolAddress((void**)&ph,    g_h);
    cudaGetSymbolAddress((void**)&pskip, g_skip);
    cudaGetSymbolAddress((void**)&phf,   g_hf);
    cudaGetSymbolAddress((void**)&pt1,   g_t1);
    cudaGetSymbolAddress((void**)&pxoe,  g_xoe);
    cudaGetSymbolAddress((void**)&pxie,  g_xie);
    cudaGetSymbolAddress((void**)&py1,   g_y1);
    cudaGetSymbolAddress((void**)&pq1,   g_q1);
    cudaGetSymbolAddress((void**)&pk2,   g_k2);
    cudaGetSymbolAddress((void**)&pk3,   g_k3);
    cudaGetSymbolAddress((void**)&pgv,   g_gv);
    cudaGetSymbolAddress((void**)&pp1,   g_p1);
    cudaGetSymbolAddress((void**)&ptwy,  g_twy);
    cudaGetSymbolAddress((void**)&ptwq,  g_twq);
    cudaGetSymbolAddress((void**)&ptw2,  g_tw2);
    cudaGetSymbolAddress((void**)&ptw3,  g_tw3);
    cudaGetSymbolAddress((void**)&ptwp,  g_twp);
    cudaGetSymbolAddress((void**)&pwd,   g_wd);
    cudaGetSymbolAddress((void**)&pbd,   g_bd);
    cudaGetSymbolAddress((void**)&pwp,   g_wp);
    cudaGetSymbolAddress((void**)&pmtot, g_mtot);

    // prep
    basis_k<<<2,384>>>();
    detect_mask_k<<<1,256>>>((const unsigned char*)nb_mask);
    count_k<<<NIN/256,256>>>(nb_mask);
    scan_k<<<1,256>>>();
    fill_k<<<NIN/256,256>>>(nb_idx, nb_mask);
    zero_stats_k<<<1,1>>>();
    {
        dim3 g((S3+255)/256, CH);
        lift_k<<<g,256>>>(df, x_out, w_lift, b_lift);
    }
    bgemm(w_skip, CH, ph, S3, b_skip, pskip, CH, CH, S3, 0, 0, 0);
    repack_k<<<(int)((25560576L+255)/256),256>>>(spec_wr, spec_wi);
    stack_k<<<(4*MDUAL*CH+255)/256,256>>>(wms, mlp1_w, bms, mlp1_b);
    transpose_k<<<(512*48 +255)/256,256>>>(k1w, ptwy, 512,  48,  96, 0,  512);
    transpose_k<<<(512*48 +255)/256,256>>>(k1w, ptwq, 512,  48,  96, 48, 512);
    transpose_k<<<(256*512+255)/256,256>>>(k2w, ptw2, 256, 512, 512, 0,  256);
    transpose_k<<<(86*256 +255)/256,256>>>(k3w, ptw3,  86, 256, 256, 0,   88);
    transpose_k<<<(256*86 +255)/256,256>>>(p1w, ptwp, 256,  86,  86, 0,  256);

    // FNO layers
    for(int l=0;l<4;l++){
        int act = (l<3) ? 1 : 0;
        if(l > 0)
            bgemm(w_skip + (size_t)l*CH*CH, CH, ph, S3, b_skip + l*CH, pskip, CH, CH, S3, 0, 0, 0);
        dft_z_k<<<(CH*S2+31)/32, 192>>>(ph);
        dft_y_k<<<CH*S, 128>>>();
        dft_x_k<<<CH, 256>>>();
        mix_k<<<NMODE, 96>>>(pwp + (size_t)l*WLAYER);
        inv_x_k<<<CH, 256>>>();
        inv_y_k<<<CH*S, 128>>>();
        inv_z_k<<<CH*S, 256>>>();
        finalize_stats_k<<<1,1>>>();
        combine_k<<<((CS>>2)+255)/256,256>>>((const float4*)phf,(const float4*)pskip,
                                             g1w + l*CH, g1b + l*CH, (float4*)ph, act);
        // fused mskip + mlp1: rows 0..85 -> pskip (no act), rows 86..171 -> pt1 (gelu)
        bgemm_dual(pwd + (size_t)l*MDUAL*CH, ph, pbd + (size_t)l*MDUAL, pskip, pt1);
        bgemm(mlp2_w + (size_t)l*CH*CH, CH, pt1, S3, mlp2_b + l*CH, phf, CH, CH, S3, 0, 0, 1);
        finalize_stats_k<<<1,1>>>();
        combine_k<<<((CS>>2)+255)/256,256>>>((const float4*)phf,(const float4*)pskip,
                                             g2w + l*CH, g2b + l*CH, (float4*)ph, act);
    }

    // crop f_y
    {
        dim3 g((NOUT+255)/256, CH);
        crop_k<<<g,256>>>();
    }

    // row-major embeddings
    embed_k<<<(NOUT+127)/128,128>>>(x_out, pxoe, NOUT);
    embed_k<<<(NIN +127)/128,128>>>(x_in,  pxie, NIN);

    // GNO kernel MLP on compacted rows
    bgemm(pxoe, 48, ptwy, 512, 0,   py1, NOUT, 48, 512, 0, 1, 0);
    bgemm(pxie, 48, ptwq, 512, k1b, pq1, NIN,  48, 512, 0, 1, 0);
    // k2 with gather+gelu A fused (k1 never materialized)
    {
        dim3 grid((256+127)/128, (RTOT+127)/128);
        bgemm_k<1,1,0,0,1><<<grid,256>>>(0, 0, ptw2, 256, k2b, pk2, 0,
                                         RTOT, 512, 256, pmtot);
    }
    bgemm(pk2, 256, ptw3,  88, k3b, pk3, RTOT, 256, CH,  0, 1, 0, pmtot);

    // masked neighbor reduce
    gno_reduce_k<<<NIN, 96>>>();

    // projection MLP
    bgemm(pgv, CH, ptwp, 256, p1b, pp1, NIN, CH, 256, 1, 1, 0);
    p2_k<<<NIN/8,256>>>(p2w, p2b, out);
}